// round 1
// baseline (speedup 1.0000x reference)
#include <cuda_runtime.h>
#include <math.h>

// ---------------- problem constants ----------------
#define MROI   64
#define GPTS   8192        // 64*32*4
#define GXC    64
#define GYC    32
#define GZC    4
#define CDIM   128
#define NKERN  147         // 7*7*3
#define NZ     10
#define NY     400
#define NX     352
#define NCELL  (NZ*NY*NX)  // 1408000
#define NVOX   200000
#define CAP    2048        // per-ROI valid-point capacity (~1.1K expected, 30 sigma margin)
#define USTR   160         // padded row stride for U (147 -> 160)

// ---------------- device scratch (allowed: __device__ globals) ----------------
__device__ int   g_v2p[NCELL];                 // 5.6 MB
__device__ int   g_cnt[MROI];
__device__ int   g_qlist[MROI * CAP];          // grid-point index of each valid point
__device__ int   g_vox[MROI * CAP];            // voxel row of each valid point
__device__ float g_U[MROI * CAP * USTR];       // 84 MB: U[m][slot][k]

// ---------------- helpers ----------------
__device__ __forceinline__ void grid_point_world(const float* __restrict__ r, int p,
                                                 float& wx, float& wy, float& wz) {
    // r = roi row (7 floats). Box dims 3,4 extended by 2.0 (matches reference).
    float cx = r[0], cy = r[1], cz = r[2];
    float dx = r[3] * 2.0f, dy = r[4] * 2.0f, dz = r[5];
    float ang = r[6];
    // precise sin/cos (immune to --use_fast_math remap of cosf -> __cosf)
    float cc = (float)cos((double)ang);
    float ss = (float)sin((double)ang);
    int i = p >> 7;          // GY*GZ = 128
    int j = (p >> 2) & 31;
    int k = p & 3;
    float lx = ((i + 0.5f) / 64.0f) * dx - dx * 0.5f;
    float ly = ((j + 0.5f) / 32.0f) * dy - dy * 0.5f;
    float lz = ((k + 0.5f) / 4.0f)  * dz - dz * 0.5f;
    // pts @ R with R = [[c,s,0],[-s,c,0],[0,0,1]]
    wx = lx * cc - ly * ss + cx;
    wy = lx * ss + ly * cc + cy;
    wz = lz + cz;
}

// ---------------- kernel 1: init scratch ----------------
__global__ __launch_bounds__(256) void k_init() {
    int i = blockIdx.x * blockDim.x + threadIdx.x;
    if (i < MROI) g_cnt[i] = 0;
    for (int j = i; j < NCELL; j += gridDim.x * blockDim.x) g_v2p[j] = -1;
}

// ---------------- kernel 2: scatter voxel ids (last-write-wins == max id) ----------------
__global__ __launch_bounds__(256) void k_scatter(const int* __restrict__ vc) {
    int i = blockIdx.x * blockDim.x + threadIdx.x;
    if (i >= NVOX) return;
    int zc = vc[i * 4 + 1];
    int yc = vc[i * 4 + 2];
    int xc = vc[i * 4 + 3];
    atomicMax(&g_v2p[(zc * NY + yc) * NX + xc], i);
}

// ---------------- kernel 3: per (roi, grid-point) -> compact valid points ----------------
__global__ __launch_bounds__(256) void k_points(const float* __restrict__ rois) {
    int gid = blockIdx.x * blockDim.x + threadIdx.x;
    if (gid >= MROI * GPTS) return;
    int m = gid >> 13;           // /8192
    int p = gid & (GPTS - 1);
    float wx, wy, wz;
    grid_point_world(rois + m * 7, p, wx, wy, wz);
    // two-step floor binning, IEEE-rounded division (matches jax fp32 exactly)
    float fx = floorf(__fdiv_rn(wx - 0.0f,  0.05f));
    float fy = floorf(__fdiv_rn(wy + 40.0f, 0.05f));
    float fz = floorf(__fdiv_rn(wz + 3.0f,  0.1f));
    int xc = (int)floorf(fx * 0.25f);
    int yc = (int)floorf(fy * 0.25f);
    int zc = (int)floorf(fz * 0.25f);
    if (zc < 0 || zc >= NZ || yc < 0 || yc >= NY || xc < 0 || xc >= NX) return;
    int pidx = g_v2p[(zc * NY + yc) * NX + xc];
    if (pidx < 0) return;
    int slot = atomicAdd(&g_cnt[m], 1);
    if (slot < CAP) {
        g_qlist[m * CAP + slot] = p;
        g_vox[m * CAP + slot]   = pidx;
    }
}

// ---------------- kernel 4: gathered GEMM  U[m][slot][k] = feat[vox[slot]] . w[k] ----------------
#define BM 64
#define BN 64
#define CH 64
#define ASTR 68   // padded smem row

__global__ __launch_bounds__(256) void k_gemm(const float* __restrict__ vfeat,
                                              const float* __restrict__ w) {
    int m = blockIdx.z;
    int cnt = min(g_cnt[m], CAP);
    int q0 = blockIdx.x * BM;
    if (q0 >= cnt) return;
    int k0 = blockIdx.y * BN;

    __shared__ float As[CH][ASTR];  // [c][q]
    __shared__ float Bs[CH][ASTR];  // [c][k]

    int t  = threadIdx.x;
    int tx = t & 15;     // q group
    int ty = t >> 4;     // k group

    // loader mapping: 4 threads per row, 16 c's each
    int lr = t >> 2;
    int lc = (t & 3) * 16;
    int slot = q0 + lr;
    const float* frow = (slot < cnt) ? (vfeat + (size_t)g_vox[m * CAP + slot] * CDIM) : nullptr;
    int kk = k0 + lr;
    const float* wrow = (kk < NKERN) ? (w + (size_t)kk * CDIM) : nullptr;

    float acc[4][4] = {};

    for (int ch = 0; ch < 2; ch++) {
        int cb = ch * CH + lc;
        #pragma unroll
        for (int u = 0; u < 16; u += 4) {
            float4 va = frow ? *(const float4*)(frow + cb + u) : make_float4(0.f, 0.f, 0.f, 0.f);
            As[lc + u + 0][lr] = va.x;
            As[lc + u + 1][lr] = va.y;
            As[lc + u + 2][lr] = va.z;
            As[lc + u + 3][lr] = va.w;
            float4 vb = wrow ? *(const float4*)(wrow + cb + u) : make_float4(0.f, 0.f, 0.f, 0.f);
            Bs[lc + u + 0][lr] = vb.x;
            Bs[lc + u + 1][lr] = vb.y;
            Bs[lc + u + 2][lr] = vb.z;
            Bs[lc + u + 3][lr] = vb.w;
        }
        __syncthreads();

        #pragma unroll 8
        for (int cc = 0; cc < CH; cc++) {
            float4 a = *(const float4*)&As[cc][tx * 4];
            float4 b = *(const float4*)&Bs[cc][ty * 4];
            acc[0][0] += a.x * b.x; acc[0][1] += a.x * b.y; acc[0][2] += a.x * b.z; acc[0][3] += a.x * b.w;
            acc[1][0] += a.y * b.x; acc[1][1] += a.y * b.y; acc[1][2] += a.y * b.z; acc[1][3] += a.y * b.w;
            acc[2][0] += a.z * b.x; acc[2][1] += a.z * b.y; acc[2][2] += a.z * b.z; acc[2][3] += a.z * b.w;
            acc[3][0] += a.w * b.x; acc[3][1] += a.w * b.y; acc[3][2] += a.w * b.z; acc[3][3] += a.w * b.w;
        }
        __syncthreads();
    }

    #pragma unroll
    for (int i = 0; i < 4; i++) {
        int s = q0 + tx * 4 + i;
        if (s >= cnt) continue;
        float* urow = &g_U[((size_t)m * CAP + s) * USTR];
        #pragma unroll
        for (int j = 0; j < 4; j++) {
            int k2 = k0 + ty * 4 + j;
            if (k2 < NKERN) urow[k2] = acc[i][j];
        }
    }
}

// ---------------- kernel 5: shift-scatter into mm (smem), argmax, emit ----------------
__global__ __launch_bounds__(256) void k_final(const float* __restrict__ rois,
                                               const float* __restrict__ proto,
                                               float* __restrict__ out) {
    __shared__ float mm[GPTS];       // 32 KB
    __shared__ float rv[256];
    __shared__ int   ri[256];

    int m = blockIdx.x;
    int t = threadIdx.x;
    for (int i = t; i < GPTS; i += 256) mm[i] = 0.0f;
    __syncthreads();

    int cnt = min(g_cnt[m], CAP);
    for (int s = t; s < cnt; s += 256) {
        int p = g_qlist[m * CAP + s];
        int x = p >> 7, y = (p >> 2) & 31, z = p & 3;
        const float* urow = &g_U[((size_t)m * CAP + s) * USTR];
        #pragma unroll 1
        for (int kx = 0; kx < 7; kx++) {
            int txx = x + 3 - kx;
            if (txx < 0 || txx >= GXC) continue;
            #pragma unroll
            for (int ky = 0; ky < 7; ky++) {
                int tyy = y + 3 - ky;
                if (tyy < 0 || tyy >= GYC) continue;
                #pragma unroll
                for (int kz = 0; kz < 3; kz++) {
                    int tzz = z + 1 - kz;
                    if (tzz < 0 || tzz >= GZC) continue;
                    float v = urow[(kx * 7 + ky) * 3 + kz];
                    atomicAdd(&mm[(txx << 7) + (tyy << 2) + tzz], v);
                }
            }
        }
    }
    __syncthreads();

    // argmax (first index on ties; normalization skipped: monotone)
    float bv = -INFINITY; int bi = GPTS;
    for (int i = t; i < GPTS; i += 256) {
        float v = mm[i];
        if (v > bv) { bv = v; bi = i; }
    }
    rv[t] = bv; ri[t] = bi;
    __syncthreads();
    if (t == 0) {
        float best = rv[0]; int bidx = ri[0];
        for (int u = 1; u < 256; u++) {
            if (rv[u] > best || (rv[u] == best && ri[u] < bidx)) { best = rv[u]; bidx = ri[u]; }
        }
        float wx, wy, wz;
        grid_point_world(rois + m * 7, bidx, wx, wy, wz);
        out[m * 7 + 0] = wx;
        out[m * 7 + 1] = wy;
        out[m * 7 + 2] = wz;
        out[m * 7 + 3] = proto[3];
        out[m * 7 + 4] = proto[4];
        out[m * 7 + 5] = proto[5];
        out[m * 7 + 6] = proto[6];
    }
}

// ---------------- launcher ----------------
extern "C" void kernel_launch(void* const* d_in, const int* in_sizes, int n_in,
                              void* d_out, int out_size) {
    const float* rois    = (const float*)d_in[0];
    const float* proto   = (const float*)d_in[1];
    const float* vfeat   = (const float*)d_in[2];
    const float* fproto  = (const float*)d_in[3];   // (KX,KY,KZ,C) contiguous -> w[k][c]
    const int*   vcoords = (const int*)d_in[4];
    float* out = (float*)d_out;

    k_init<<<2048, 256>>>();
    k_scatter<<<(NVOX + 255) / 256, 256>>>(vcoords);
    k_points<<<(MROI * GPTS + 255) / 256, 256>>>(rois);
    dim3 gg(CAP / BM, 3, MROI);   // 32 x 3 x 64 (inactive tiles early-exit)
    k_gemm<<<gg, 256>>>(vfeat, fproto);
    k_final<<<MROI, 256>>>(rois, proto, out);
}

// round 2
// speedup vs baseline: 1.1666x; 1.1666x over previous
#include <cuda_runtime.h>
#include <math.h>

// ---------------- problem constants ----------------
#define MROI   64
#define GPTS   8192        // 64*32*4
#define GXC    64
#define GYC    32
#define GZC    4
#define CDIM   128
#define NKERN  147         // 7*7*3
#define NZ     10
#define NY     400
#define NX     352
#define NCELL  (NZ*NY*NX)  // 1408000
#define NVOX   200000
#define CAP    2048        // per-ROI valid-point capacity (~1.1K expected)
#define USTR   196         // U row: 49 (kx,ky) groups x 4 (kz padded) floats
#define CSTR   36          // smem row stride (floats) for GEMM tiles

// ---------------- device scratch ----------------
__device__ int    g_v2p[NCELL];
__device__ int    g_cnt[MROI];
__device__ int    g_qlist[MROI * CAP];
__device__ int    g_vox[MROI * CAP];
__device__ float2 g_trig[MROI];               // (cos, sin) per ROI
__device__ float  g_U[MROI * CAP * USTR];     // ~103 MB

// ---------------- helpers ----------------
__device__ __forceinline__ void grid_point_world_f(const float* __restrict__ r,
                                                   float cc, float ss, int p,
                                                   float& wx, float& wy, float& wz) {
    float dx = r[3] * 2.0f, dy = r[4] * 2.0f, dz = r[5];
    int i = p >> 7;
    int j = (p >> 2) & 31;
    int k = p & 3;
    float lx = ((i + 0.5f) / 64.0f) * dx - dx * 0.5f;
    float ly = ((j + 0.5f) / 32.0f) * dy - dy * 0.5f;
    float lz = ((k + 0.5f) / 4.0f)  * dz - dz * 0.5f;
    wx = lx * cc - ly * ss + r[0];
    wy = lx * ss + ly * cc + r[1];
    wz = lz + r[2];
}

__device__ __forceinline__ unsigned long long ffma2(unsigned long long a,
                                                    unsigned long long b,
                                                    unsigned long long c) {
    unsigned long long d;
    asm("fma.rn.f32x2 %0, %1, %2, %3;" : "=l"(d) : "l"(a), "l"(b), "l"(c));
    return d;
}

// ---------------- kernel 1: init scratch + per-ROI trig ----------------
__global__ __launch_bounds__(256) void k_init(const float* __restrict__ rois) {
    int i = blockIdx.x * blockDim.x + threadIdx.x;
    if (blockIdx.x == 0 && threadIdx.x < MROI) {
        g_cnt[threadIdx.x] = 0;
        double ang = (double)rois[threadIdx.x * 7 + 6];
        g_trig[threadIdx.x] = make_float2((float)cos(ang), (float)sin(ang));
    }
    for (int j = i; j < NCELL; j += gridDim.x * blockDim.x) g_v2p[j] = -1;
}

// ---------------- kernel 2: scatter voxel ids (last-write-wins == max id) ----------------
__global__ __launch_bounds__(256) void k_scatter(const int* __restrict__ vc) {
    int i = blockIdx.x * blockDim.x + threadIdx.x;
    if (i >= NVOX) return;
    int zc = vc[i * 4 + 1];
    int yc = vc[i * 4 + 2];
    int xc = vc[i * 4 + 3];
    atomicMax(&g_v2p[(zc * NY + yc) * NX + xc], i);
}

// ---------------- kernel 3: compact valid (roi, grid-point) pairs ----------------
__global__ __launch_bounds__(256) void k_points(const float* __restrict__ rois) {
    int gid = blockIdx.x * blockDim.x + threadIdx.x;
    if (gid >= MROI * GPTS) return;
    int m = gid >> 13;
    int p = gid & (GPTS - 1);
    float2 tg = g_trig[m];
    float wx, wy, wz;
    grid_point_world_f(rois + m * 7, tg.x, tg.y, p, wx, wy, wz);
    float fx = floorf(__fdiv_rn(wx - 0.0f,  0.05f));
    float fy = floorf(__fdiv_rn(wy + 40.0f, 0.05f));
    float fz = floorf(__fdiv_rn(wz + 3.0f,  0.1f));
    int xc = (int)floorf(fx * 0.25f);
    int yc = (int)floorf(fy * 0.25f);
    int zc = (int)floorf(fz * 0.25f);
    if (zc < 0 || zc >= NZ || yc < 0 || yc >= NY || xc < 0 || xc >= NX) return;
    int pidx = g_v2p[(zc * NY + yc) * NX + xc];
    if (pidx < 0) return;
    int slot = atomicAdd(&g_cnt[m], 1);
    if (slot < CAP) {
        g_qlist[m * CAP + slot] = p;
        g_vox[m * CAP + slot]   = pidx;
    }
}

// ---------------- kernel 4: gathered GEMM with packed f32x2 FMA ----------------
// Block tile: 64 q-rows x 160 k-cols (covers 147), C chunked by 32.
// Thread grid 8x32 (tx,ty), micro-tile 8x5, pack dim = channel pairs.
__global__ __launch_bounds__(256) void k_gemm(const float* __restrict__ vfeat,
                                              const float* __restrict__ w) {
    int m = blockIdx.y;
    int cnt = min(g_cnt[m], CAP);
    int q0 = blockIdx.x * 64;
    if (q0 >= cnt) return;

    __shared__ float As[64 * CSTR];    // [row][c] row-major, CSTR=36 pad
    __shared__ float Bs[160 * CSTR];
    __shared__ int   rowv[64];

    int t  = threadIdx.x;
    int tx = t & 7;
    int ty = t >> 3;

    if (t < 64) rowv[t] = (q0 + t < cnt) ? g_vox[m * CAP + q0 + t] : -1;
    __syncthreads();

    unsigned long long acc[8][5];
    #pragma unroll
    for (int i = 0; i < 8; i++)
        #pragma unroll
        for (int j = 0; j < 5; j++) acc[i][j] = 0ull;

    for (int ch = 0; ch < 4; ch++) {
        int cb = ch * 32;
        // load A chunk: 64 rows x 32 floats = 512 float4 granules, 2/thread
        #pragma unroll
        for (int g = t; g < 512; g += 256) {
            int row = g >> 3, c4 = (g & 7) * 4;
            int vr = rowv[row];
            float4 v = make_float4(0.f, 0.f, 0.f, 0.f);
            if (vr >= 0) v = *(const float4*)(vfeat + (size_t)vr * CDIM + cb + c4);
            *(float4*)&As[row * CSTR + c4] = v;
        }
        // load B chunk: 160 rows x 32 floats = 1280 granules, 5/thread
        #pragma unroll
        for (int g = t; g < 1280; g += 256) {
            int row = g >> 3, c4 = (g & 7) * 4;
            float4 v = make_float4(0.f, 0.f, 0.f, 0.f);
            if (row < NKERN) v = *(const float4*)(w + (size_t)row * CDIM + cb + c4);
            *(float4*)&Bs[row * CSTR + c4] = v;
        }
        __syncthreads();

        #pragma unroll
        for (int cc2 = 0; cc2 < 16; cc2++) {
            unsigned long long a2[8], b2[5];
            #pragma unroll
            for (int i = 0; i < 8; i++)
                a2[i] = *(const unsigned long long*)&As[(tx + 8 * i) * CSTR + cc2 * 2];
            #pragma unroll
            for (int j = 0; j < 5; j++)
                b2[j] = *(const unsigned long long*)&Bs[(ty + 32 * j) * CSTR + cc2 * 2];
            #pragma unroll
            for (int i = 0; i < 8; i++)
                #pragma unroll
                for (int j = 0; j < 5; j++)
                    acc[i][j] = ffma2(a2[i], b2[j], acc[i][j]);
        }
        __syncthreads();
    }

    // epilogue: write U in kz-padded layout (group = k/3 at stride 4)
    #pragma unroll
    for (int i = 0; i < 8; i++) {
        int s = q0 + tx + 8 * i;
        if (s >= cnt) continue;
        float* urow = &g_U[((size_t)m * CAP + s) * USTR];
        #pragma unroll
        for (int j = 0; j < 5; j++) {
            int k = ty + 32 * j;
            if (k < NKERN) {
                float2 f = *(float2*)&acc[i][j];
                urow[(k / 3) * 4 + (k % 3)] = f.x + f.y;
            }
        }
    }
}

// ---------------- kernel 5: gather-conv + fused argmax + emit ----------------
__global__ __launch_bounds__(256) void k_final(const float* __restrict__ rois,
                                               const float* __restrict__ proto,
                                               float* __restrict__ out) {
    __shared__ int   slotmap[GPTS];     // 32 KB
    __shared__ float rv[256];
    __shared__ int   ri[256];

    int m = blockIdx.x;
    int t = threadIdx.x;
    int cnt = min(g_cnt[m], CAP);

    for (int i = t; i < GPTS; i += 256) slotmap[i] = -1;
    __syncthreads();
    for (int s = t; s < cnt; s += 256) slotmap[g_qlist[m * CAP + s]] = s;
    __syncthreads();

    const float* ubase = &g_U[(size_t)m * CAP * USTR];

    float bv = -INFINITY; int bi = GPTS;
    // 2048 (X,Y) columns, 8 per thread, ascending for first-index ties
    for (int c = t; c < GXC * GYC; c += 256) {
        int X = c >> 5, Y = c & 31;
        float a0 = 0.f, a1 = 0.f, a2v = 0.f, a3 = 0.f;
        #pragma unroll 1
        for (int dx = -3; dx <= 3; dx++) {
            int xp = X + dx;
            if (xp < 0 || xp >= GXC) continue;
            int kxg = (dx + 3) * 7;
            #pragma unroll
            for (int dy = -3; dy <= 3; dy++) {
                int yp = Y + dy;
                if (yp < 0 || yp >= GYC) continue;
                int goff = (kxg + dy + 3) * 4;
                int4 sl = *(const int4*)&slotmap[(xp << 7) + (yp << 2)];
                if (sl.x >= 0) {   // z'=0: kz2->z=-1(skip), kz1->z=0, kz0->z=1
                    const float* u = ubase + (size_t)sl.x * USTR + goff;
                    a0 += u[1]; a1 += u[0];
                }
                if (sl.y >= 0) {   // z'=1
                    const float* u = ubase + (size_t)sl.y * USTR + goff;
                    a0 += u[2]; a1 += u[1]; a2v += u[0];
                }
                if (sl.z >= 0) {   // z'=2
                    const float* u = ubase + (size_t)sl.z * USTR + goff;
                    a1 += u[2]; a2v += u[1]; a3 += u[0];
                }
                if (sl.w >= 0) {   // z'=3
                    const float* u = ubase + (size_t)sl.w * USTR + goff;
                    a2v += u[2]; a3 += u[1];
                }
            }
        }
        int pb = (X << 7) + (Y << 2);
        if (a0 > bv) { bv = a0; bi = pb; }
        if (a1 > bv) { bv = a1; bi = pb + 1; }
        if (a2v > bv) { bv = a2v; bi = pb + 2; }
        if (a3 > bv) { bv = a3; bi = pb + 3; }
    }
    rv[t] = bv; ri[t] = bi;
    __syncthreads();
    if (t == 0) {
        float best = rv[0]; int bidx = ri[0];
        for (int u = 1; u < 256; u++) {
            if (rv[u] > best || (rv[u] == best && ri[u] < bidx)) { best = rv[u]; bidx = ri[u]; }
        }
        float2 tg = g_trig[m];
        float wx, wy, wz;
        grid_point_world_f(rois + m * 7, tg.x, tg.y, bidx, wx, wy, wz);
        out[m * 7 + 0] = wx;
        out[m * 7 + 1] = wy;
        out[m * 7 + 2] = wz;
        out[m * 7 + 3] = proto[3];
        out[m * 7 + 4] = proto[4];
        out[m * 7 + 5] = proto[5];
        out[m * 7 + 6] = proto[6];
    }
}

// ---------------- launcher ----------------
extern "C" void kernel_launch(void* const* d_in, const int* in_sizes, int n_in,
                              void* d_out, int out_size) {
    const float* rois    = (const float*)d_in[0];
    const float* proto   = (const float*)d_in[1];
    const float* vfeat   = (const float*)d_in[2];
    const float* fproto  = (const float*)d_in[3];
    const int*   vcoords = (const int*)d_in[4];
    float* out = (float*)d_out;

    k_init<<<2048, 256>>>(rois);
    k_scatter<<<(NVOX + 255) / 256, 256>>>(vcoords);
    k_points<<<(MROI * GPTS + 255) / 256, 256>>>(rois);
    dim3 gg(CAP / 64, MROI);
    k_gemm<<<gg, 256>>>(vfeat, fproto);
    k_final<<<MROI, 256>>>(rois, proto, out);
}

// round 4
// speedup vs baseline: 1.4385x; 1.2331x over previous
#include <cuda_runtime.h>
#include <math.h>

// ---------------- problem constants ----------------
#define MROI   64
#define GPTS   8192        // 64*32*4
#define GXC    64
#define GYC    32
#define GZC    4
#define CDIM   128
#define NKERN  147         // 7*7*3
#define NZ     10
#define NY     400
#define NX     352
#define NCELL  (NZ*NY*NX)
#define NVOX   200000
#define CAP    2048
#define USTR   196         // 49 (kx,ky) groups x 4 (kz padded)
#define CSTR   36

// ---------------- device scratch ----------------
__device__ int                g_v2p[NCELL];
__device__ int                g_cnt[MROI];
__device__ int                g_qlist[MROI * CAP];
__device__ int                g_vox[MROI * CAP];
__device__ float2             g_trig[MROI];
__device__ unsigned long long g_best[MROI];
__device__ float              g_U[MROI * CAP * USTR];

// ---------------- helpers ----------------
__device__ __forceinline__ void grid_point_world_f(const float* __restrict__ r,
                                                   float cc, float ss, int p,
                                                   float& wx, float& wy, float& wz) {
    float dx = r[3] * 2.0f, dy = r[4] * 2.0f, dz = r[5];
    int i = p >> 7;
    int j = (p >> 2) & 31;
    int k = p & 3;
    float lx = ((i + 0.5f) / 64.0f) * dx - dx * 0.5f;
    float ly = ((j + 0.5f) / 32.0f) * dy - dy * 0.5f;
    float lz = ((k + 0.5f) / 4.0f)  * dz - dz * 0.5f;
    wx = lx * cc - ly * ss + r[0];
    wy = lx * ss + ly * cc + r[1];
    wz = lz + r[2];
}

__device__ __forceinline__ unsigned long long ffma2(unsigned long long a,
                                                    unsigned long long b,
                                                    unsigned long long c) {
    unsigned long long d;
    asm("fma.rn.f32x2 %0, %1, %2, %3;" : "=l"(d) : "l"(a), "l"(b), "l"(c));
    return d;
}

__device__ __forceinline__ unsigned int ord_float(float f) {
    unsigned int u = __float_as_uint(f);
    return (u & 0x80000000u) ? ~u : (u | 0x80000000u);
}

// ---------------- kernel 1: init ----------------
__global__ __launch_bounds__(256) void k_init(const float* __restrict__ rois) {
    int i = blockIdx.x * blockDim.x + threadIdx.x;
    if (blockIdx.x == 0 && threadIdx.x < MROI) {
        g_cnt[threadIdx.x] = 0;
        g_best[threadIdx.x] = 0ull;
        double ang = (double)rois[threadIdx.x * 7 + 6];
        g_trig[threadIdx.x] = make_float2((float)cos(ang), (float)sin(ang));
    }
    for (int j = i; j < NCELL; j += gridDim.x * blockDim.x) g_v2p[j] = -1;
}

// ---------------- kernel 2: voxel scatter ----------------
__global__ __launch_bounds__(256) void k_scatter(const int* __restrict__ vc) {
    int i = blockIdx.x * blockDim.x + threadIdx.x;
    if (i >= NVOX) return;
    int zc = vc[i * 4 + 1];
    int yc = vc[i * 4 + 2];
    int xc = vc[i * 4 + 3];
    atomicMax(&g_v2p[(zc * NY + yc) * NX + xc], i);
}

// ---------------- kernel 3: compact valid points ----------------
__global__ __launch_bounds__(256) void k_points(const float* __restrict__ rois) {
    int gid = blockIdx.x * blockDim.x + threadIdx.x;
    if (gid >= MROI * GPTS) return;
    int m = gid >> 13;
    int p = gid & (GPTS - 1);
    float2 tg = g_trig[m];
    float wx, wy, wz;
    grid_point_world_f(rois + m * 7, tg.x, tg.y, p, wx, wy, wz);
    float fx = floorf(__fdiv_rn(wx - 0.0f,  0.05f));
    float fy = floorf(__fdiv_rn(wy + 40.0f, 0.05f));
    float fz = floorf(__fdiv_rn(wz + 3.0f,  0.1f));
    int xc = (int)floorf(fx * 0.25f);
    int yc = (int)floorf(fy * 0.25f);
    int zc = (int)floorf(fz * 0.25f);
    if (zc < 0 || zc >= NZ || yc < 0 || yc >= NY || xc < 0 || xc >= NX) return;
    int pidx = g_v2p[(zc * NY + yc) * NX + xc];
    if (pidx < 0) return;
    int slot = atomicAdd(&g_cnt[m], 1);
    if (slot < CAP) {
        g_qlist[m * CAP + slot] = p;
        g_vox[m * CAP + slot]   = pidx;
    }
}

// ---------------- kernel 4: gathered GEMM, f32x2, 2 CTAs/SM ----------------
__global__ __launch_bounds__(256, 2) void k_gemm(const float* __restrict__ vfeat,
                                                 const float* __restrict__ w) {
    int m = blockIdx.y;
    int cnt = min(g_cnt[m], CAP);
    int q0 = blockIdx.x * 64;
    if (q0 >= cnt) return;

    __shared__ float As[64 * CSTR];
    __shared__ float Bs[160 * CSTR];
    __shared__ int   rowv[64];

    int t  = threadIdx.x;
    int tx = t & 7;
    int ty = t >> 3;

    if (t < 64) rowv[t] = (q0 + t < cnt) ? g_vox[m * CAP + q0 + t] : -1;
    __syncthreads();

    unsigned long long acc[8][5];
    #pragma unroll
    for (int i = 0; i < 8; i++)
        #pragma unroll
        for (int j = 0; j < 5; j++) acc[i][j] = 0ull;

    const float* abase = &As[tx * CSTR];
    const float* bbase = &Bs[ty * CSTR];

    for (int ch = 0; ch < 4; ch++) {
        int cb = ch * 32;
        {
            int row = t >> 3, c4 = (t & 7) * 4;
            int vr0 = rowv[row];
            float4 va0 = make_float4(0.f, 0.f, 0.f, 0.f);
            if (vr0 >= 0) va0 = *(const float4*)(vfeat + (size_t)vr0 * CDIM + cb + c4);
            *(float4*)&As[row * CSTR + c4] = va0;
            int vr1 = rowv[row + 32];
            float4 va1 = make_float4(0.f, 0.f, 0.f, 0.f);
            if (vr1 >= 0) va1 = *(const float4*)(vfeat + (size_t)vr1 * CDIM + cb + c4);
            *(float4*)&As[(row + 32) * CSTR + c4] = va1;
            #pragma unroll
            for (int rr = 0; rr < 5; rr++) {
                int br = row + 32 * rr;
                float4 vb = make_float4(0.f, 0.f, 0.f, 0.f);
                if (br < NKERN) vb = *(const float4*)(w + (size_t)br * CDIM + cb + c4);
                *(float4*)&Bs[br * CSTR + c4] = vb;
            }
        }
        __syncthreads();

        #pragma unroll
        for (int cc2 = 0; cc2 < 16; cc2++) {
            unsigned long long a2[8], b2[5];
            #pragma unroll
            for (int i = 0; i < 8; i++)
                a2[i] = *(const unsigned long long*)(abase + (8 * i) * CSTR + cc2 * 2);
            #pragma unroll
            for (int j = 0; j < 5; j++)
                b2[j] = *(const unsigned long long*)(bbase + (32 * j) * CSTR + cc2 * 2);
            #pragma unroll
            for (int i = 0; i < 8; i++)
                #pragma unroll
                for (int j = 0; j < 5; j++)
                    acc[i][j] = ffma2(a2[i], b2[j], acc[i][j]);
        }
        __syncthreads();
    }

    #pragma unroll
    for (int i = 0; i < 8; i++) {
        int s = q0 + tx + 8 * i;
        if (s >= cnt) continue;
        float* urow = &g_U[((size_t)m * CAP + s) * USTR];
        #pragma unroll
        for (int j = 0; j < 5; j++) {
            int k = ty + 32 * j;
            if (k < NKERN) {
                float2 f = *(float2*)&acc[i][j];
                urow[(k / 3) * 4 + (k % 3)] = f.x + f.y;
            }
        }
    }
}

// ---------------- kernel 5: slab-scatter conv + fused argmax ----------------
__global__ __launch_bounds__(256) void k_conv() {
    __shared__ float              mm[1024];        // 8 X x 32 Y x 4 Z
    __shared__ unsigned long long rk[256];

    int m  = blockIdx.y;
    int x0 = blockIdx.x * 8;
    int t  = threadIdx.x;
    int cnt = min(g_cnt[m], CAP);

    for (int i = t; i < 1024; i += 256) mm[i] = 0.0f;
    __syncthreads();

    const float* ubase = &g_U[(size_t)m * CAP * USTR];

    for (int s = t; s < cnt; s += 256) {
        int p = g_qlist[m * CAP + s];
        int x = p >> 7, y = (p >> 2) & 31, z = p & 3;
        if (x < x0 - 3 || x > x0 + 10) continue;
        const float* urow = ubase + (size_t)s * USTR;
        #pragma unroll 1
        for (int dx = -3; dx <= 3; dx++) {
            int xl = x + dx - x0;
            if (xl < 0 || xl >= 8) continue;
            int kxg = (3 - dx) * 7;
            #pragma unroll
            for (int dy = -3; dy <= 3; dy++) {
                int yy = y + dy;
                if (yy < 0 || yy >= GYC) continue;
                float4 u = *(const float4*)(urow + (kxg + 3 - dy) * 4);
                int base = (xl << 7) + (yy << 2) + z;
                // dz=-1 -> kz=2 (u.z), dz=0 -> kz=1 (u.y), dz=+1 -> kz=0 (u.x)
                if (z >= 1)  atomicAdd(&mm[base - 1], u.z);
                atomicAdd(&mm[base], u.y);
                if (z <= 2)  atomicAdd(&mm[base + 1], u.x);
            }
        }
    }
    __syncthreads();

    unsigned long long best = 0ull;
    for (int i = t; i < 1024; i += 256) {
        int p = ((x0 + (i >> 7)) << 7) | (i & 127);
        unsigned long long key =
            ((unsigned long long)ord_float(mm[i]) << 32) | (unsigned int)(~p);
        if (key > best) best = key;
    }
    rk[t] = best;
    __syncthreads();
    if (t < 128) { if (rk[t + 128] > rk[t]) rk[t] = rk[t + 128]; }
    __syncthreads();
    if (t < 64)  { if (rk[t + 64]  > rk[t]) rk[t] = rk[t + 64]; }
    __syncthreads();
    if (t < 32) {
        unsigned long long b = rk[t];
        if (rk[t + 32] > b) b = rk[t + 32];
        #pragma unroll
        for (int o = 16; o > 0; o >>= 1) {
            unsigned long long other = __shfl_down_sync(0xFFFFFFFFu, b, o);
            if (other > b) b = other;
        }
        if (t == 0) atomicMax(&g_best[m], b);
    }
}

// ---------------- kernel 6: emit ----------------
__global__ __launch_bounds__(64) void k_emit(const float* __restrict__ rois,
                                             const float* __restrict__ proto,
                                             float* __restrict__ out) {
    int m = threadIdx.x;
    if (m >= MROI) return;
    unsigned long long key = g_best[m];
    int p = (int)(~(unsigned int)(key & 0xFFFFFFFFull));
    float2 tg = g_trig[m];
    float wx, wy, wz;
    grid_point_world_f(rois + m * 7, tg.x, tg.y, p, wx, wy, wz);
    out[m * 7 + 0] = wx;
    out[m * 7 + 1] = wy;
    out[m * 7 + 2] = wz;
    out[m * 7 + 3] = proto[3];
    out[m * 7 + 4] = proto[4];
    out[m * 7 + 5] = proto[5];
    out[m * 7 + 6] = proto[6];
}

// ---------------- launcher ----------------
extern "C" void kernel_launch(void* const* d_in, const int* in_sizes, int n_in,
                              void* d_out, int out_size) {
    const float* rois    = (const float*)d_in[0];
    const float* proto   = (const float*)d_in[1];
    const float* vfeat   = (const float*)d_in[2];
    const float* fproto  = (const float*)d_in[3];
    const int*   vcoords = (const int*)d_in[4];
    float* out = (float*)d_out;

    k_init<<<2048, 256>>>(rois);
    k_scatter<<<(NVOX + 255) / 256, 256>>>(vcoords);
    k_points<<<(MROI * GPTS + 255) / 256, 256>>>(rois);
    dim3 gg(CAP / 64, MROI);
    k_gemm<<<gg, 256>>>(vfeat, fproto);
    dim3 gc(8, MROI);
    k_conv<<<gc, 256>>>();
    k_emit<<<1, 64>>>(rois, proto, out);
}

// round 6
// speedup vs baseline: 1.5644x; 1.0875x over previous
#include <cuda_runtime.h>
#include <math.h>
#include <cstdint>

// ---------------- problem constants ----------------
#define MROI   64
#define GPTS   8192        // 64*32*4
#define GXC    64
#define GYC    32
#define GZC    4
#define CDIM   128
#define NKERN  147         // 7*7*3
#define NZ     10
#define NY     400
#define NX     352
#define NCELL  (NZ*NY*NX)
#define NVOX   200000
#define CAP    2048
#define USTR   196         // 49 (kx,ky) groups x 4 (kz padded)
#define CSTR   36          // smem row stride (floats); 144 B = 16-aligned

// ---------------- device scratch ----------------
__device__ int                g_v2p[NCELL];
__device__ int                g_cnt[MROI];
__device__ int                g_qlist[MROI * CAP];
__device__ int                g_vox[MROI * CAP];
__device__ float2             g_trig[MROI];
__device__ unsigned long long g_best[MROI];
__device__ float              g_U[MROI * CAP * USTR];

// ---------------- helpers ----------------
__device__ __forceinline__ void grid_point_world_f(const float* __restrict__ r,
                                                   float cc, float ss, int p,
                                                   float& wx, float& wy, float& wz) {
    float dx = r[3] * 2.0f, dy = r[4] * 2.0f, dz = r[5];
    int i = p >> 7;
    int j = (p >> 2) & 31;
    int k = p & 3;
    float lx = ((i + 0.5f) / 64.0f) * dx - dx * 0.5f;
    float ly = ((j + 0.5f) / 32.0f) * dy - dy * 0.5f;
    float lz = ((k + 0.5f) / 4.0f)  * dz - dz * 0.5f;
    wx = lx * cc - ly * ss + r[0];
    wy = lx * ss + ly * cc + r[1];
    wz = lz + r[2];
}

__device__ __forceinline__ unsigned long long ffma2(unsigned long long a,
                                                    unsigned long long b,
                                                    unsigned long long c) {
    unsigned long long d;
    asm("fma.rn.f32x2 %0, %1, %2, %3;" : "=l"(d) : "l"(a), "l"(b), "l"(c));
    return d;
}

__device__ __forceinline__ unsigned int ord_float(float f) {
    unsigned int u = __float_as_uint(f);
    return (u & 0x80000000u) ? ~u : (u | 0x80000000u);
}

__device__ __forceinline__ uint32_t smem_u32(const void* p) {
    uint32_t a;
    asm("{ .reg .u64 t; cvta.to.shared.u64 t, %1; cvt.u32.u64 %0, t; }" : "=r"(a) : "l"(p));
    return a;
}
__device__ __forceinline__ void cp_async16(uint32_t s, const void* g) {
    asm volatile("cp.async.cg.shared.global [%0], [%1], 16;" :: "r"(s), "l"(g));
}
#define CP_COMMIT()  asm volatile("cp.async.commit_group;" ::: "memory")
#define CP_WAIT(n)   asm volatile("cp.async.wait_group %0;" :: "n"(n) : "memory")

// ---------------- kernel 1: init ----------------
__global__ __launch_bounds__(256) void k_init(const float* __restrict__ rois) {
    int i = blockIdx.x * blockDim.x + threadIdx.x;
    if (blockIdx.x == 0 && threadIdx.x < MROI) {
        g_cnt[threadIdx.x] = 0;
        g_best[threadIdx.x] = 0ull;
        double ang = (double)rois[threadIdx.x * 7 + 6];
        g_trig[threadIdx.x] = make_float2((float)cos(ang), (float)sin(ang));
    }
    for (int j = i; j < NCELL; j += gridDim.x * blockDim.x) g_v2p[j] = -1;
}

// ---------------- kernel 2: voxel scatter ----------------
__global__ __launch_bounds__(256) void k_scatter(const int* __restrict__ vc) {
    int i = blockIdx.x * blockDim.x + threadIdx.x;
    if (i >= NVOX) return;
    int zc = vc[i * 4 + 1];
    int yc = vc[i * 4 + 2];
    int xc = vc[i * 4 + 3];
    atomicMax(&g_v2p[(zc * NY + yc) * NX + xc], i);
}

// ---------------- kernel 3: compact valid points ----------------
__global__ __launch_bounds__(256) void k_points(const float* __restrict__ rois) {
    int gid = blockIdx.x * blockDim.x + threadIdx.x;
    if (gid >= MROI * GPTS) return;
    int m = gid >> 13;
    int p = gid & (GPTS - 1);
    float2 tg = g_trig[m];
    float wx, wy, wz;
    grid_point_world_f(rois + m * 7, tg.x, tg.y, p, wx, wy, wz);
    float fx = floorf(__fdiv_rn(wx - 0.0f,  0.05f));
    float fy = floorf(__fdiv_rn(wy + 40.0f, 0.05f));
    float fz = floorf(__fdiv_rn(wz + 3.0f,  0.1f));
    int xc = (int)floorf(fx * 0.25f);
    int yc = (int)floorf(fy * 0.25f);
    int zc = (int)floorf(fz * 0.25f);
    if (zc < 0 || zc >= NZ || yc < 0 || yc >= NY || xc < 0 || xc >= NX) return;
    int pidx = g_v2p[(zc * NY + yc) * NX + xc];
    if (pidx < 0) return;
    int slot = atomicAdd(&g_cnt[m], 1);
    if (slot < CAP) {
        g_qlist[m * CAP + slot] = p;
        g_vox[m * CAP + slot]   = pidx;
    }
}

// ---------------- kernel 4: gathered GEMM, f32x2, cp.async double-buffered ----------------
__global__ __launch_bounds__(256, 2) void k_gemm(const float* __restrict__ vfeat,
                                                 const float* __restrict__ w) {
    int m = blockIdx.y;
    int cnt = min(g_cnt[m], CAP);
    int q0 = blockIdx.x * 64;
    if (q0 >= cnt) return;

    __shared__ float As[2][64 * CSTR];
    __shared__ float Bs[2][160 * CSTR];
    __shared__ int   rowv[64];

    int t   = threadIdx.x;
    int tx  = t & 7;
    int ty  = t >> 3;
    int row = t >> 3;          // 0..31 (loader row)
    int c4  = (t & 7) * 4;     // loader channel offset

    if (t < 64) rowv[t] = (q0 + t < cnt) ? g_vox[m * CAP + q0 + t] : -1;
    __syncthreads();

    int vr0 = rowv[row];
    int vr1 = rowv[row + 32];
    const float* fr0 = vfeat + (size_t)max(vr0, 0) * CDIM + c4;
    const float* fr1 = vfeat + (size_t)max(vr1, 0) * CDIM + c4;

    // pre-zero invalid rows in BOTH buffers (cp.async never touches them)
    {
        float4 z4 = make_float4(0.f, 0.f, 0.f, 0.f);
        if (vr0 < 0) {
            *(float4*)&As[0][row * CSTR + c4] = z4;
            *(float4*)&As[1][row * CSTR + c4] = z4;
        }
        if (vr1 < 0) {
            *(float4*)&As[0][(row + 32) * CSTR + c4] = z4;
            *(float4*)&As[1][(row + 32) * CSTR + c4] = z4;
        }
        #pragma unroll
        for (int rr = 0; rr < 5; rr++) {
            int br = row + 32 * rr;
            if (br >= NKERN) {
                *(float4*)&Bs[0][br * CSTR + c4] = z4;
                *(float4*)&Bs[1][br * CSTR + c4] = z4;
            }
        }
    }

    unsigned long long acc[8][5];
    #pragma unroll
    for (int i = 0; i < 8; i++)
        #pragma unroll
        for (int j = 0; j < 5; j++) acc[i][j] = 0ull;

    uint32_t sA0[2], sA1[2], sB[2];
    sA0[0] = smem_u32(&As[0][row * CSTR + c4]);
    sA0[1] = smem_u32(&As[1][row * CSTR + c4]);
    sA1[0] = smem_u32(&As[0][(row + 32) * CSTR + c4]);
    sA1[1] = smem_u32(&As[1][(row + 32) * CSTR + c4]);
    sB[0]  = smem_u32(&Bs[0][row * CSTR + c4]);
    sB[1]  = smem_u32(&Bs[1][row * CSTR + c4]);

    // issue copies for channel-chunk ch into buffer buf
    #define ISSUE(ch, buf) do {                                                   \
        int _cb = (ch) * 32;                                                      \
        if (vr0 >= 0) cp_async16(sA0[buf], fr0 + _cb);                            \
        if (vr1 >= 0) cp_async16(sA1[buf], fr1 + _cb);                            \
        _Pragma("unroll")                                                         \
        for (int rr = 0; rr < 5; rr++) {                                          \
            int br = row + 32 * rr;                                               \
            if (br < NKERN)                                                       \
                cp_async16(sB[buf] + rr * 32 * CSTR * 4,                          \
                           w + (size_t)br * CDIM + _cb + c4);                     \
        }                                                                         \
    } while (0)

    ISSUE(0, 0); CP_COMMIT();

    #pragma unroll
    for (int ch = 0; ch < 4; ch++) {
        if (ch < 3) { ISSUE(ch + 1, (ch + 1) & 1); CP_COMMIT(); CP_WAIT(1); }
        else        { CP_WAIT(0); }
        __syncthreads();

        const float* abase = &As[ch & 1][tx * CSTR];
        const float* bbase = &Bs[ch & 1][ty * CSTR];
        #pragma unroll
        for (int cc2 = 0; cc2 < 16; cc2++) {
            unsigned long long a2[8], b2[5];
            #pragma unroll
            for (int i = 0; i < 8; i++)
                a2[i] = *(const unsigned long long*)(abase + (8 * i) * CSTR + cc2 * 2);
            #pragma unroll
            for (int j = 0; j < 5; j++)
                b2[j] = *(const unsigned long long*)(bbase + (32 * j) * CSTR + cc2 * 2);
            #pragma unroll
            for (int i = 0; i < 8; i++)
                #pragma unroll
                for (int j = 0; j < 5; j++)
                    acc[i][j] = ffma2(a2[i], b2[j], acc[i][j]);
        }
        __syncthreads();
    }
    #undef ISSUE

    #pragma unroll
    for (int i = 0; i < 8; i++) {
        int s = q0 + tx + 8 * i;
        if (s >= cnt) continue;
        float* urow = &g_U[((size_t)m * CAP + s) * USTR];
        #pragma unroll
        for (int j = 0; j < 5; j++) {
            int k = ty + 32 * j;
            if (k < NKERN) {
                float2 f = *(float2*)&acc[i][j];
                urow[(k / 3) * 4 + (k % 3)] = f.x + f.y;
            }
        }
    }
}

// ---------------- kernel 5: slab-scatter conv + fused argmax ----------------
__global__ __launch_bounds__(256) void k_conv() {
    __shared__ float              mm[1024];        // 8 X x 32 Y x 4 Z
    __shared__ unsigned long long rk[256];

    int m  = blockIdx.y;
    int x0 = blockIdx.x * 8;
    int t  = threadIdx.x;
    int cnt = min(g_cnt[m], CAP);

    for (int i = t; i < 1024; i += 256) mm[i] = 0.0f;
    __syncthreads();

    const float* ubase = &g_U[(size_t)m * CAP * USTR];

    for (int s = t; s < cnt; s += 256) {
        int p = g_qlist[m * CAP + s];
        int x = p >> 7, y = (p >> 2) & 31, z = p & 3;
        if (x < x0 - 3 || x > x0 + 10) continue;
        const float* urow = ubase + (size_t)s * USTR;
        #pragma unroll 1
        for (int dx = -3; dx <= 3; dx++) {
            int xl = x + dx - x0;
            if (xl < 0 || xl >= 8) continue;
            int kxg = (3 - dx) * 7;
            #pragma unroll
            for (int dy = -3; dy <= 3; dy++) {
                int yy = y + dy;
                if (yy < 0 || yy >= GYC) continue;
                float4 u = *(const float4*)(urow + (kxg + 3 - dy) * 4);
                int basei = (xl << 7) + (yy << 2) + z;
                if (z >= 1)  atomicAdd(&mm[basei - 1], u.z);
                atomicAdd(&mm[basei], u.y);
                if (z <= 2)  atomicAdd(&mm[basei + 1], u.x);
            }
        }
    }
    __syncthreads();

    unsigned long long best = 0ull;
    for (int i = t; i < 1024; i += 256) {
        int p = ((x0 + (i >> 7)) << 7) | (i & 127);
        unsigned long long key =
            ((unsigned long long)ord_float(mm[i]) << 32) | (unsigned int)(~p);
        if (key > best) best = key;
    }
    rk[t] = best;
    __syncthreads();
    if (t < 128) { if (rk[t + 128] > rk[t]) rk[t] = rk[t + 128]; }
    __syncthreads();
    if (t < 64)  { if (rk[t + 64]  > rk[t]) rk[t] = rk[t + 64]; }
    __syncthreads();
    if (t < 32) {
        unsigned long long b = rk[t];
        if (rk[t + 32] > b) b = rk[t + 32];
        #pragma unroll
        for (int o = 16; o > 0; o >>= 1) {
            unsigned long long other = __shfl_down_sync(0xFFFFFFFFu, b, o);
            if (other > b) b = other;
        }
        if (t == 0) atomicMax(&g_best[m], b);
    }
}

// ---------------- kernel 6: emit ----------------
__global__ __launch_bounds__(64) void k_emit(const float* __restrict__ rois,
                                             const float* __restrict__ proto,
                                             float* __restrict__ out) {
    int m = threadIdx.x;
    if (m >= MROI) return;
    unsigned long long key = g_best[m];
    int p = (int)(~(unsigned int)(key & 0xFFFFFFFFull));
    float2 tg = g_trig[m];
    float wx, wy, wz;
    grid_point_world_f(rois + m * 7, tg.x, tg.y, p, wx, wy, wz);
    out[m * 7 + 0] = wx;
    out[m * 7 + 1] = wy;
    out[m * 7 + 2] = wz;
    out[m * 7 + 3] = proto[3];
    out[m * 7 + 4] = proto[4];
    out[m * 7 + 5] = proto[5];
    out[m * 7 + 6] = proto[6];
}

// ---------------- launcher ----------------
extern "C" void kernel_launch(void* const* d_in, const int* in_sizes, int n_in,
                              void* d_out, int out_size) {
    const float* rois    = (const float*)d_in[0];
    const float* proto   = (const float*)d_in[1];
    const float* vfeat   = (const float*)d_in[2];
    const float* fproto  = (const float*)d_in[3];
    const int*   vcoords = (const int*)d_in[4];
    float* out = (float*)d_out;

    k_init<<<2048, 256>>>(rois);
    k_scatter<<<(NVOX + 255) / 256, 256>>>(vcoords);
    k_points<<<(MROI * GPTS + 255) / 256, 256>>>(rois);
    dim3 gg(CAP / 64, MROI);
    k_gemm<<<gg, 256>>>(vfeat, fproto);
    dim3 gc(8, MROI);
    k_conv<<<gc, 256>>>();
    k_emit<<<1, 64>>>(rois, proto, out);
}

// round 7
// speedup vs baseline: 1.6176x; 1.0340x over previous
#include <cuda_runtime.h>
#include <math.h>
#include <cstdint>

// ---------------- problem constants ----------------
#define MROI   64
#define GPTS   8192        // 64*32*4
#define GXC    64
#define GYC    32
#define GZC    4
#define CDIM   128
#define NKERN  147         // 7*7*3
#define NZ     10
#define NY     400
#define NX     352
#define NCELL  (NZ*NY*NX)
#define NVOX   200000
#define CAP    2048
#define USTR   196         // 49 (kx,ky) groups x 4 (kz padded)
#define CSTR   36          // smem row stride (floats); 144 B, 16B-aligned
#define SLABW  16          // k_conv slab width in X

// ---------------- device scratch ----------------
__device__ int                g_v2p[NCELL];
__device__ int                g_cnt[MROI];
__device__ int                g_qlist[MROI * CAP];
__device__ int                g_vox[MROI * CAP];
__device__ float2             g_trig[MROI];
__device__ unsigned long long g_best[MROI];
__device__ float              g_U[MROI * CAP * USTR];

// ---------------- helpers ----------------
__device__ __forceinline__ void grid_point_world_f(const float* __restrict__ r,
                                                   float cc, float ss, int p,
                                                   float& wx, float& wy, float& wz) {
    float dx = r[3] * 2.0f, dy = r[4] * 2.0f, dz = r[5];
    int i = p >> 7;
    int j = (p >> 2) & 31;
    int k = p & 3;
    float lx = ((i + 0.5f) / 64.0f) * dx - dx * 0.5f;
    float ly = ((j + 0.5f) / 32.0f) * dy - dy * 0.5f;
    float lz = ((k + 0.5f) / 4.0f)  * dz - dz * 0.5f;
    wx = lx * cc - ly * ss + r[0];
    wy = lx * ss + ly * cc + r[1];
    wz = lz + r[2];
}

__device__ __forceinline__ unsigned long long ffma2(unsigned long long a,
                                                    unsigned long long b,
                                                    unsigned long long c) {
    unsigned long long d;
    asm("fma.rn.f32x2 %0, %1, %2, %3;" : "=l"(d) : "l"(a), "l"(b), "l"(c));
    return d;
}

__device__ __forceinline__ unsigned int ord_float(float f) {
    unsigned int u = __float_as_uint(f);
    return (u & 0x80000000u) ? ~u : (u | 0x80000000u);
}

__device__ __forceinline__ uint32_t smem_u32(const void* p) {
    uint32_t a;
    asm("{ .reg .u64 t; cvta.to.shared.u64 t, %1; cvt.u32.u64 %0, t; }" : "=r"(a) : "l"(p));
    return a;
}
__device__ __forceinline__ void cp_async16(uint32_t s, const void* g) {
    asm volatile("cp.async.cg.shared.global [%0], [%1], 16;" :: "r"(s), "l"(g));
}
#define CP_COMMIT()  asm volatile("cp.async.commit_group;" ::: "memory")
#define CP_WAIT(n)   asm volatile("cp.async.wait_group %0;" :: "n"(n) : "memory")

// ---------------- kernel 1: init ----------------
__global__ __launch_bounds__(256) void k_init(const float* __restrict__ rois) {
    int i = blockIdx.x * blockDim.x + threadIdx.x;
    if (blockIdx.x == 0 && threadIdx.x < MROI) {
        g_cnt[threadIdx.x] = 0;
        g_best[threadIdx.x] = 0ull;
        double ang = (double)rois[threadIdx.x * 7 + 6];
        g_trig[threadIdx.x] = make_float2((float)cos(ang), (float)sin(ang));
    }
    for (int j = i; j < NCELL; j += gridDim.x * blockDim.x) g_v2p[j] = -1;
}

// ---------------- kernel 2: voxel scatter ----------------
__global__ __launch_bounds__(256) void k_scatter(const int* __restrict__ vc) {
    int i = blockIdx.x * blockDim.x + threadIdx.x;
    if (i >= NVOX) return;
    int zc = vc[i * 4 + 1];
    int yc = vc[i * 4 + 2];
    int xc = vc[i * 4 + 3];
    atomicMax(&g_v2p[(zc * NY + yc) * NX + xc], i);
}

// ---------------- kernel 3: compact valid points (warp-aggregated) ----------------
__global__ __launch_bounds__(256) void k_points(const float* __restrict__ rois) {
    int gid = blockIdx.x * blockDim.x + threadIdx.x;     // grid is exact
    int m = gid >> 13;
    int p = gid & (GPTS - 1);
    int lane = threadIdx.x & 31;

    float2 tg = g_trig[m];
    float wx, wy, wz;
    grid_point_world_f(rois + m * 7, tg.x, tg.y, p, wx, wy, wz);
    float fx = floorf(__fdiv_rn(wx - 0.0f,  0.05f));
    float fy = floorf(__fdiv_rn(wy + 40.0f, 0.05f));
    float fz = floorf(__fdiv_rn(wz + 3.0f,  0.1f));
    int xc = (int)floorf(fx * 0.25f);
    int yc = (int)floorf(fy * 0.25f);
    int zc = (int)floorf(fz * 0.25f);

    bool valid = false;
    int pidx = -1;
    if (zc >= 0 && zc < NZ && yc >= 0 && yc < NY && xc >= 0 && xc < NX) {
        pidx = g_v2p[(zc * NY + yc) * NX + xc];
        valid = (pidx >= 0);
    }
    unsigned mask = __ballot_sync(0xFFFFFFFFu, valid);
    if (valid) {
        int leader = __ffs(mask) - 1;
        int base = 0;
        if (lane == leader) base = atomicAdd(&g_cnt[m], __popc(mask));
        base = __shfl_sync(mask, base, leader);
        int slot = base + __popc(mask & ((1u << lane) - 1u));
        if (slot < CAP) {
            g_qlist[m * CAP + slot] = p;
            g_vox[m * CAP + slot]   = pidx;
        }
    }
}

// ---------------- kernel 4: gathered GEMM, f32x2, cp.async, LDS.128 B ----------------
__global__ __launch_bounds__(256, 2) void k_gemm(const float* __restrict__ vfeat,
                                                 const float* __restrict__ w) {
    int m = blockIdx.y;
    int cnt = min(g_cnt[m], CAP);
    int q0 = blockIdx.x * 64;
    if (q0 >= cnt) return;

    __shared__ float As[2][64 * CSTR];
    __shared__ float Bs[2][160 * CSTR];
    __shared__ int   rowv[64];

    int t   = threadIdx.x;
    int tx  = t & 7;
    int ty  = t >> 3;
    int row = t >> 3;          // loader row 0..31
    int c4  = (t & 7) * 4;     // loader channel offset

    if (t < 64) rowv[t] = (q0 + t < cnt) ? g_vox[m * CAP + q0 + t] : -1;
    __syncthreads();

    int vr0 = rowv[row];
    int vr1 = rowv[row + 32];
    const float* fr0 = vfeat + (size_t)max(vr0, 0) * CDIM + c4;
    const float* fr1 = vfeat + (size_t)max(vr1, 0) * CDIM + c4;

    // pre-zero invalid rows in both buffers
    {
        float4 z4 = make_float4(0.f, 0.f, 0.f, 0.f);
        if (vr0 < 0) {
            *(float4*)&As[0][row * CSTR + c4] = z4;
            *(float4*)&As[1][row * CSTR + c4] = z4;
        }
        if (vr1 < 0) {
            *(float4*)&As[0][(row + 32) * CSTR + c4] = z4;
            *(float4*)&As[1][(row + 32) * CSTR + c4] = z4;
        }
        #pragma unroll
        for (int rr = 0; rr < 5; rr++) {
            int br = row + 32 * rr;
            if (br >= NKERN) {
                *(float4*)&Bs[0][br * CSTR + c4] = z4;
                *(float4*)&Bs[1][br * CSTR + c4] = z4;
            }
        }
    }

    unsigned long long acc[8][5];
    #pragma unroll
    for (int i = 0; i < 8; i++)
        #pragma unroll
        for (int j = 0; j < 5; j++) acc[i][j] = 0ull;

    uint32_t sA0[2], sA1[2], sB[2];
    sA0[0] = smem_u32(&As[0][row * CSTR + c4]);
    sA0[1] = smem_u32(&As[1][row * CSTR + c4]);
    sA1[0] = smem_u32(&As[0][(row + 32) * CSTR + c4]);
    sA1[1] = smem_u32(&As[1][(row + 32) * CSTR + c4]);
    sB[0]  = smem_u32(&Bs[0][row * CSTR + c4]);
    sB[1]  = smem_u32(&Bs[1][row * CSTR + c4]);

    #define ISSUE(ch, buf) do {                                                   \
        int _cb = (ch) * 32;                                                      \
        if (vr0 >= 0) cp_async16(sA0[buf], fr0 + _cb);                            \
        if (vr1 >= 0) cp_async16(sA1[buf], fr1 + _cb);                            \
        _Pragma("unroll")                                                         \
        for (int rr = 0; rr < 5; rr++) {                                          \
            int br = row + 32 * rr;                                               \
            if (br < NKERN)                                                       \
                cp_async16(sB[buf] + rr * 32 * CSTR * 4,                          \
                           w + (size_t)br * CDIM + _cb + c4);                     \
        }                                                                         \
    } while (0)

    ISSUE(0, 0); CP_COMMIT();

    #pragma unroll
    for (int ch = 0; ch < 4; ch++) {
        if (ch < 3) { ISSUE(ch + 1, (ch + 1) & 1); CP_COMMIT(); CP_WAIT(1); }
        else        { CP_WAIT(0); }
        __syncthreads();

        const float* abase = &As[ch & 1][tx * CSTR];
        const float* bbase = &Bs[ch & 1][ty * CSTR];
        #pragma unroll
        for (int cc4 = 0; cc4 < 8; cc4++) {
            float4 b4[5];
            #pragma unroll
            for (int j = 0; j < 5; j++)
                b4[j] = *(const float4*)(bbase + (32 * j) * CSTR + cc4 * 4);
            #pragma unroll
            for (int half = 0; half < 2; half++) {
                unsigned long long a2[8];
                #pragma unroll
                for (int i = 0; i < 8; i++)
                    a2[i] = *(const unsigned long long*)(abase + (8 * i) * CSTR + cc4 * 4 + half * 2);
                #pragma unroll
                for (int i = 0; i < 8; i++)
                    #pragma unroll
                    for (int j = 0; j < 5; j++)
                        acc[i][j] = ffma2(a2[i],
                                          ((const unsigned long long*)&b4[j])[half],
                                          acc[i][j]);
            }
        }
        __syncthreads();
    }
    #undef ISSUE

    #pragma unroll
    for (int i = 0; i < 8; i++) {
        int s = q0 + tx + 8 * i;
        if (s >= cnt) continue;
        float* urow = &g_U[((size_t)m * CAP + s) * USTR];
        #pragma unroll
        for (int j = 0; j < 5; j++) {
            int k = ty + 32 * j;
            if (k < NKERN) {
                float2 f = *(float2*)&acc[i][j];
                urow[(k / 3) * 4 + (k % 3)] = f.x + f.y;
            }
        }
    }
}

// ---------------- kernel 5: slab-scatter conv + fused argmax (16-wide slabs) ----------------
__global__ __launch_bounds__(256) void k_conv() {
    __shared__ float              mm[SLABW * 128];   // 16 X x 32 Y x 4 Z = 8 KB
    __shared__ unsigned long long rk[256];

    int m  = blockIdx.y;
    int x0 = blockIdx.x * SLABW;
    int t  = threadIdx.x;
    int cnt = min(g_cnt[m], CAP);

    for (int i = t; i < SLABW * 128; i += 256) mm[i] = 0.0f;
    __syncthreads();

    const float* ubase = &g_U[(size_t)m * CAP * USTR];

    for (int s = t; s < cnt; s += 256) {
        int p = g_qlist[m * CAP + s];
        int x = p >> 7, y = (p >> 2) & 31, z = p & 3;
        if (x < x0 - 3 || x > x0 + SLABW + 2) continue;
        const float* urow = ubase + (size_t)s * USTR;
        #pragma unroll 1
        for (int dx = -3; dx <= 3; dx++) {
            int xl = x + dx - x0;
            if (xl < 0 || xl >= SLABW) continue;
            int kxg = (3 - dx) * 7;
            #pragma unroll
            for (int dy = -3; dy <= 3; dy++) {
                int yy = y + dy;
                if (yy < 0 || yy >= GYC) continue;
                float4 u = *(const float4*)(urow + (kxg + 3 - dy) * 4);
                int basei = (xl << 7) + (yy << 2) + z;
                if (z >= 1)  atomicAdd(&mm[basei - 1], u.z);
                atomicAdd(&mm[basei], u.y);
                if (z <= 2)  atomicAdd(&mm[basei + 1], u.x);
            }
        }
    }
    __syncthreads();

    unsigned long long best = 0ull;
    for (int i = t; i < SLABW * 128; i += 256) {
        int p = ((x0 + (i >> 7)) << 7) | (i & 127);
        unsigned long long key =
            ((unsigned long long)ord_float(mm[i]) << 32) | (unsigned int)(~p);
        if (key > best) best = key;
    }
    rk[t] = best;
    __syncthreads();
    if (t < 128) { if (rk[t + 128] > rk[t]) rk[t] = rk[t + 128]; }
    __syncthreads();
    if (t < 64)  { if (rk[t + 64]  > rk[t]) rk[t] = rk[t + 64]; }
    __syncthreads();
    if (t < 32) {
        unsigned long long b = rk[t];
        if (rk[t + 32] > b) b = rk[t + 32];
        #pragma unroll
        for (int o = 16; o > 0; o >>= 1) {
            unsigned long long other = __shfl_down_sync(0xFFFFFFFFu, b, o);
            if (other > b) b = other;
        }
        if (t == 0) atomicMax(&g_best[m], b);
    }
}

// ---------------- kernel 6: emit ----------------
__global__ __launch_bounds__(64) void k_emit(const float* __restrict__ rois,
                                             const float* __restrict__ proto,
                                             float* __restrict__ out) {
    int m = threadIdx.x;
    if (m >= MROI) return;
    unsigned long long key = g_best[m];
    int p = (int)(~(unsigned int)(key & 0xFFFFFFFFull));
    float2 tg = g_trig[m];
    float wx, wy, wz;
    grid_point_world_f(rois + m * 7, tg.x, tg.y, p, wx, wy, wz);
    out[m * 7 + 0] = wx;
    out[m * 7 + 1] = wy;
    out[m * 7 + 2] = wz;
    out[m * 7 + 3] = proto[3];
    out[m * 7 + 4] = proto[4];
    out[m * 7 + 5] = proto[5];
    out[m * 7 + 6] = proto[6];
}

// ---------------- launcher ----------------
extern "C" void kernel_launch(void* const* d_in, const int* in_sizes, int n_in,
                              void* d_out, int out_size) {
    const float* rois    = (const float*)d_in[0];
    const float* proto   = (const float*)d_in[1];
    const float* vfeat   = (const float*)d_in[2];
    const float* fproto  = (const float*)d_in[3];
    const int*   vcoords = (const int*)d_in[4];
    float* out = (float*)d_out;

    k_init<<<2048, 256>>>(rois);
    k_scatter<<<(NVOX + 255) / 256, 256>>>(vcoords);
    k_points<<<MROI * GPTS / 256, 256>>>(rois);
    dim3 gg(CAP / 64, MROI);
    k_gemm<<<gg, 256>>>(vfeat, fproto);
    dim3 gc(GXC / SLABW, MROI);
    k_conv<<<gc, 256>>>();
    k_emit<<<1, 64>>>(rois, proto, out);
}

// round 9
// speedup vs baseline: 1.9504x; 1.2058x over previous
#include <cuda_runtime.h>
#include <cuda_bf16.h>
#include <math.h>
#include <cstdint>

// ---------------- problem constants ----------------
#define MROI   64
#define GPTS   8192        // 64*32*4
#define GXC    64
#define GYC    32
#define GZC    4
#define CDIM   128
#define NKERN  147         // 7*7*3
#define NZ     10
#define NY     400
#define NX     352
#define NCELL  (NZ*NY*NX)
#define NVOX   200000
#define CAP    2048
#define USTR   196         // 49 (kx,ky) groups x 4 (kz padded)
#define SLABW  16          // k_conv slab width in X

#define NB     160         // padded B rows
#define ASTR   36          // A smem row stride (floats), 144 B
#define BSTRH  40          // B smem row stride (uint16), 80 B

// dynamic smem layout for k_gemm (per CTA): 88064 B
#define A_OFF(b)    ((b) * 18432)                  // 128*36*4
#define BHI_OFF(b)  (36864 + (b) * 12800)          // 160*80
#define BLO_OFF(b)  (62464 + (b) * 12800)
#define GEMM_SMEM   88064

// ---------------- device scratch ----------------
__device__ int                g_v2p[NCELL];
__device__ int                g_cnt[MROI];
__device__ int                g_qlist[MROI * CAP];
__device__ int                g_vox[MROI * CAP];
__device__ float2             g_trig[MROI];
__device__ unsigned long long g_best[MROI];
__device__ float              g_U[MROI * CAP * USTR];
__device__ unsigned short     g_Whi[NB * CDIM];
__device__ unsigned short     g_Wlo[NB * CDIM];

// ---------------- helpers ----------------
__device__ __forceinline__ void grid_point_world_f(const float* __restrict__ r,
                                                   float cc, float ss, int p,
                                                   float& wx, float& wy, float& wz) {
    float dx = r[3] * 2.0f, dy = r[4] * 2.0f, dz = r[5];
    int i = p >> 7;
    int j = (p >> 2) & 31;
    int k = p & 3;
    float lx = ((i + 0.5f) / 64.0f) * dx - dx * 0.5f;
    float ly = ((j + 0.5f) / 32.0f) * dy - dy * 0.5f;
    float lz = ((k + 0.5f) / 4.0f)  * dz - dz * 0.5f;
    wx = lx * cc - ly * ss + r[0];
    wy = lx * ss + ly * cc + r[1];
    wz = lz + r[2];
}

__device__ __forceinline__ unsigned int ord_float(float f) {
    unsigned int u = __float_as_uint(f);
    return (u & 0x80000000u) ? ~u : (u | 0x80000000u);
}

__device__ __forceinline__ uint32_t smem_u32(const void* p) {
    uint32_t a;
    asm("{ .reg .u64 t; cvta.to.shared.u64 t, %1; cvt.u32.u64 %0, t; }" : "=r"(a) : "l"(p));
    return a;
}
__device__ __forceinline__ void cp_async16(uint32_t s, const void* g) {
    asm volatile("cp.async.cg.shared.global [%0], [%1], 16;" :: "r"(s), "l"(g));
}
#define CP_COMMIT()  asm volatile("cp.async.commit_group;" ::: "memory")
#define CP_WAIT(n)   asm volatile("cp.async.wait_group %0;" :: "n"(n) : "memory")

// pack two fp32 into bf16x2 (rn), lower = f0
__device__ __forceinline__ uint32_t pack_bf16x2(float f0, float f1) {
    uint32_t r;
    asm("cvt.rn.bf16x2.f32 %0, %2, %1;" : "=r"(r) : "f"(f0), "f"(f1));
    return r;
}
// split a float pair into hi/lo bf16x2
__device__ __forceinline__ void split_pair(float f0, float f1, uint32_t& hi, uint32_t& lo) {
    hi = pack_bf16x2(f0, f1);
    float h0 = __uint_as_float(hi << 16);
    float h1 = __uint_as_float(hi & 0xFFFF0000u);
    lo = pack_bf16x2(f0 - h0, f1 - h1);
}

__device__ __forceinline__ void mma_bf16(float* c, const uint32_t* a, uint32_t b0, uint32_t b1) {
    asm volatile("mma.sync.aligned.m16n8k16.row.col.f32.bf16.bf16.f32 "
                 "{%0,%1,%2,%3}, {%4,%5,%6,%7}, {%8,%9}, {%0,%1,%2,%3};"
                 : "+f"(c[0]), "+f"(c[1]), "+f"(c[2]), "+f"(c[3])
                 : "r"(a[0]), "r"(a[1]), "r"(a[2]), "r"(a[3]), "r"(b0), "r"(b1));
}

// ---------------- kernel 1: init ----------------
__global__ __launch_bounds__(256) void k_init(const float* __restrict__ rois) {
    int i = blockIdx.x * blockDim.x + threadIdx.x;
    if (blockIdx.x == 0 && threadIdx.x < MROI) {
        g_cnt[threadIdx.x] = 0;
        g_best[threadIdx.x] = 0ull;
        double ang = (double)rois[threadIdx.x * 7 + 6];
        g_trig[threadIdx.x] = make_float2((float)cos(ang), (float)sin(ang));
    }
    for (int j = i; j < NCELL; j += gridDim.x * blockDim.x) g_v2p[j] = -1;
}

// ---------------- kernel 2: voxel scatter ----------------
__global__ __launch_bounds__(256) void k_scatter(const int* __restrict__ vc) {
    int i = blockIdx.x * blockDim.x + threadIdx.x;
    if (i >= NVOX) return;
    int zc = vc[i * 4 + 1];
    int yc = vc[i * 4 + 2];
    int xc = vc[i * 4 + 3];
    atomicMax(&g_v2p[(zc * NY + yc) * NX + xc], i);
}

// ---------------- kernel 3: compact valid points (warp-aggregated) ----------------
__global__ __launch_bounds__(256) void k_points(const float* __restrict__ rois) {
    int gid = blockIdx.x * blockDim.x + threadIdx.x;
    int m = gid >> 13;
    int p = gid & (GPTS - 1);
    int lane = threadIdx.x & 31;

    float2 tg = g_trig[m];
    float wx, wy, wz;
    grid_point_world_f(rois + m * 7, tg.x, tg.y, p, wx, wy, wz);
    float fx = floorf(__fdiv_rn(wx - 0.0f,  0.05f));
    float fy = floorf(__fdiv_rn(wy + 40.0f, 0.05f));
    float fz = floorf(__fdiv_rn(wz + 3.0f,  0.1f));
    int xc = (int)floorf(fx * 0.25f);
    int yc = (int)floorf(fy * 0.25f);
    int zc = (int)floorf(fz * 0.25f);

    bool valid = false;
    int pidx = -1;
    if (zc >= 0 && zc < NZ && yc >= 0 && yc < NY && xc >= 0 && xc < NX) {
        pidx = g_v2p[(zc * NY + yc) * NX + xc];
        valid = (pidx >= 0);
    }
    unsigned mask = __ballot_sync(0xFFFFFFFFu, valid);
    if (valid) {
        int leader = __ffs(mask) - 1;
        int base = 0;
        if (lane == leader) base = atomicAdd(&g_cnt[m], __popc(mask));
        base = __shfl_sync(mask, base, leader);
        int slot = base + __popc(mask & ((1u << lane) - 1u));
        if (slot < CAP) {
            g_qlist[m * CAP + slot] = p;
            g_vox[m * CAP + slot]   = pidx;
        }
    }
}

// ---------------- kernel 3.5: split W into bf16 hi/lo ----------------
__global__ __launch_bounds__(256) void k_prepb(const float* __restrict__ w) {
    int idx = blockIdx.x * blockDim.x + threadIdx.x;
    if (idx >= NB * CDIM) return;
    int row = idx >> 7;
    int col = idx & 127;
    float v = (row < NKERN) ? w[row * CDIM + col] : 0.0f;
    __nv_bfloat16 h = __float2bfloat16(v);
    float r = v - __bfloat162float(h);
    __nv_bfloat16 l = __float2bfloat16(r);
    g_Whi[idx] = __bfloat16_as_ushort(h);
    g_Wlo[idx] = __bfloat16_as_ushort(l);
}

// ---------------- kernel 4: split-bf16 tensor-core gathered GEMM ----------------
// Block: 128 q-rows x 160 cols. 8 warps = 4 (M) x 2 (N). Per-warp 32x80.
__global__ __launch_bounds__(256, 2) void k_gemm(const float* __restrict__ vfeat) {
    int m = blockIdx.y;
    int cnt = min(g_cnt[m], CAP);
    int q0 = blockIdx.x * 128;
    if (q0 >= cnt) return;

    extern __shared__ __align__(16) char dsm[];
    __shared__ int rowv[128];

    int t    = threadIdx.x;
    int wid  = t >> 5;
    int lane = t & 31;
    int g    = lane >> 2;
    int tt   = lane & 3;
    int mw   = wid & 3;          // M-warp: rows mw*32 .. +31
    int nw   = wid >> 2;         // N-warp: cols nw*80 .. +79
    int q0w  = mw * 32;
    int n0w  = nw * 80;

    if (t < 128) rowv[t] = (q0 + t < cnt) ? g_vox[m * CAP + q0 + t] : -1;
    __syncthreads();

    uint32_t dsm_u = smem_u32(dsm);

    // pre-zero invalid A rows in both buffers; granule gi: row=gi>>3, q16=gi&7
    #pragma unroll
    for (int i = 0; i < 4; i++) {
        int gi = t + 256 * i;
        int row = gi >> 3, q16 = gi & 7;
        if (rowv[row] < 0) {
            uint4 z = make_uint4(0u, 0u, 0u, 0u);
            *(uint4*)(dsm + A_OFF(0) + row * 144 + q16 * 16) = z;
            *(uint4*)(dsm + A_OFF(1) + row * 144 + q16 * 16) = z;
        }
    }

    #define ISSUE(ch, buf) do {                                                     \
        _Pragma("unroll")                                                           \
        for (int i = 0; i < 4; i++) {                                               \
            int gi = t + 256 * i;                                                   \
            int row = gi >> 3, q16 = gi & 7;                                        \
            int vr = rowv[row];                                                     \
            if (vr >= 0)                                                            \
                cp_async16(dsm_u + A_OFF(buf) + row * 144 + q16 * 16,               \
                           vfeat + (size_t)vr * CDIM + (ch) * 32 + q16 * 4);        \
        }                                                                           \
        _Pragma("unroll")                                                           \
        for (int i = 0; i < 5; i++) {                                               \
            int idx = t + 256 * i;                                                  \
            int mat = idx >= 640;                                                   \
            int gi = idx - (mat ? 640 : 0);                                         \
            int row = gi >> 2, q16 = gi & 3;                                        \
            const unsigned short* src = (mat ? g_Wlo : g_Whi)                       \
                                        + row * CDIM + (ch) * 32 + q16 * 8;         \
            uint32_t dst = dsm_u + (mat ? BLO_OFF(buf) : BHI_OFF(buf))              \
                           + row * 80 + q16 * 16;                                   \
            cp_async16(dst, src);                                                   \
        }                                                                           \
    } while (0)

    float acc[2][10][4];
    #pragma unroll
    for (int i = 0; i < 2; i++)
        #pragma unroll
        for (int j = 0; j < 10; j++)
            #pragma unroll
            for (int e = 0; e < 4; e++) acc[i][j][e] = 0.0f;

    ISSUE(0, 0); CP_COMMIT();

    #pragma unroll
    for (int ch = 0; ch < 4; ch++) {
        if (ch < 3) { ISSUE(ch + 1, (ch + 1) & 1); CP_COMMIT(); CP_WAIT(1); }
        else        { CP_WAIT(0); }
        __syncthreads();

        int buf = ch & 1;
        const char* abase = dsm + A_OFF(buf);
        const unsigned short* bh = (const unsigned short*)(dsm + BHI_OFF(buf));
        const unsigned short* bl = (const unsigned short*)(dsm + BLO_OFF(buf));

        #pragma unroll
        for (int ks = 0; ks < 2; ks++) {
            int k0 = ks * 16 + 2 * tt;
            // A fragments for both m-tiles (hi & lo)
            uint32_t ahi[2][4], alo[2][4];
            #pragma unroll
            for (int mt = 0; mt < 2; mt++) {
                int r0 = q0w + mt * 16 + g;
                #pragma unroll
                for (int half = 0; half < 2; half++) {
                    float2 p0 = *(const float2*)(abase + r0 * 144 + (k0 + half * 8) * 4);
                    float2 p1 = *(const float2*)(abase + (r0 + 8) * 144 + (k0 + half * 8) * 4);
                    split_pair(p0.x, p0.y, ahi[mt][half * 2],     alo[mt][half * 2]);
                    split_pair(p1.x, p1.y, ahi[mt][half * 2 + 1], alo[mt][half * 2 + 1]);
                }
            }
            #pragma unroll
            for (int nt = 0; nt < 10; nt++) {
                int n = n0w + nt * 8 + g;
                uint32_t bh0 = *(const uint32_t*)(bh + n * BSTRH + k0);
                uint32_t bh1 = *(const uint32_t*)(bh + n * BSTRH + k0 + 8);
                uint32_t bl0 = *(const uint32_t*)(bl + n * BSTRH + k0);
                uint32_t bl1 = *(const uint32_t*)(bl + n * BSTRH + k0 + 8);
                #pragma unroll
                for (int mt = 0; mt < 2; mt++) {
                    mma_bf16(acc[mt][nt], ahi[mt], bh0, bh1);
                    mma_bf16(acc[mt][nt], ahi[mt], bl0, bl1);
                    mma_bf16(acc[mt][nt], alo[mt], bh0, bh1);
                }
            }
        }
        __syncthreads();
    }
    #undef ISSUE

    // epilogue: acc -> g_U (kz-padded layout)
    #pragma unroll
    for (int mt = 0; mt < 2; mt++) {
        #pragma unroll
        for (int e2 = 0; e2 < 2; e2++) {           // row half (c0c1 vs c2c3)
            int row = q0 + q0w + mt * 16 + g + e2 * 8;
            if (row >= cnt) continue;
            float* urow = &g_U[((size_t)m * CAP + row) * USTR];
            #pragma unroll
            for (int nt = 0; nt < 10; nt++) {
                int col = n0w + nt * 8 + 2 * tt;
                if (col < NKERN)     urow[(col / 3) * 4 + col % 3] = acc[mt][nt][e2 * 2];
                int col1 = col + 1;
                if (col1 < NKERN)    urow[(col1 / 3) * 4 + col1 % 3] = acc[mt][nt][e2 * 2 + 1];
            }
        }
    }
}

// ---------------- kernel 5: slab-scatter conv + fused argmax ----------------
__global__ __launch_bounds__(256) void k_conv() {
    __shared__ float              mm[SLABW * 128];
    __shared__ unsigned long long rk[256];

    int m  = blockIdx.y;
    int x0 = blockIdx.x * SLABW;
    int t  = threadIdx.x;
    int cnt = min(g_cnt[m], CAP);

    for (int i = t; i < SLABW * 128; i += 256) mm[i] = 0.0f;
    __syncthreads();

    const float* ubase = &g_U[(size_t)m * CAP * USTR];

    for (int s = t; s < cnt; s += 256) {
        int p = g_qlist[m * CAP + s];
        int x = p >> 7, y = (p >> 2) & 31, z = p & 3;
        if (x < x0 - 3 || x > x0 + SLABW + 2) continue;
        const float* urow = ubase + (size_t)s * USTR;
        #pragma unroll 1
        for (int dx = -3; dx <= 3; dx++) {
            int xl = x + dx - x0;
            if (xl < 0 || xl >= SLABW) continue;
            int kxg = (3 - dx) * 7;
            #pragma unroll
            for (int dy = -3; dy <= 3; dy++) {
                int yy = y + dy;
                if (yy < 0 || yy >= GYC) continue;
                float4 u = *(const float4*)(urow + (kxg + 3 - dy) * 4);
                int basei = (xl << 7) + (yy << 2) + z;
                if (z >= 1)  atomicAdd(&mm[basei - 1], u.z);
                atomicAdd(&mm[basei], u.y);
                if (z <= 2)  atomicAdd(&mm[basei + 1], u.x);
            }
        }
    }
    __syncthreads();

    unsigned long long best = 0ull;
    for (int i = t; i < SLABW * 128; i += 256) {
        int p = ((x0 + (i >> 7)) << 7) | (i & 127);
        unsigned long long key =
            ((unsigned long long)ord_float(mm[i]) << 32) | (unsigned int)(~p);
        if (key > best) best = key;
    }
    rk[t] = best;
    __syncthreads();
    if (t < 128) { if (rk[t + 128] > rk[t]) rk[t] = rk[t + 128]; }
    __syncthreads();
    if (t < 64)  { if (rk[t + 64]  > rk[t]) rk[t] = rk[t + 64]; }
    __syncthreads();
    if (t < 32) {
        unsigned long long b = rk[t];
        if (rk[t + 32] > b) b = rk[t + 32];
        #pragma unroll
        for (int o = 16; o > 0; o >>= 1) {
            unsigned long long other = __shfl_down_sync(0xFFFFFFFFu, b, o);
            if (other > b) b = other;
        }
        if (t == 0) atomicMax(&g_best[m], b);
    }
}

// ---------------- kernel 6: emit ----------------
__global__ __launch_bounds__(64) void k_emit(const float* __restrict__ rois,
                                             const float* __restrict__ proto,
                                             float* __restrict__ out) {
    int m = threadIdx.x;
    if (m >= MROI) return;
    unsigned long long key = g_best[m];
    int p = (int)(~(unsigned int)(key & 0xFFFFFFFFull));
    float2 tg = g_trig[m];
    float wx, wy, wz;
    grid_point_world_f(rois + m * 7, tg.x, tg.y, p, wx, wy, wz);
    out[m * 7 + 0] = wx;
    out[m * 7 + 1] = wy;
    out[m * 7 + 2] = wz;
    out[m * 7 + 3] = proto[3];
    out[m * 7 + 4] = proto[4];
    out[m * 7 + 5] = proto[5];
    out[m * 7 + 6] = proto[6];
}

// ---------------- launcher ----------------
extern "C" void kernel_launch(void* const* d_in, const int* in_sizes, int n_in,
                              void* d_out, int out_size) {
    const float* rois    = (const float*)d_in[0];
    const float* proto   = (const float*)d_in[1];
    const float* vfeat   = (const float*)d_in[2];
    const float* fproto  = (const float*)d_in[3];
    const int*   vcoords = (const int*)d_in[4];
    float* out = (float*)d_out;

    static bool attr_set = false;
    if (!attr_set) {
        cudaFuncSetAttribute(k_gemm, cudaFuncAttributeMaxDynamicSharedMemorySize, GEMM_SMEM);
        attr_set = true;
    }

    k_init<<<2048, 256>>>(rois);
    k_scatter<<<(NVOX + 255) / 256, 256>>>(vcoords);
    k_points<<<MROI * GPTS / 256, 256>>>(rois);
    k_prepb<<<(NB * CDIM + 255) / 256, 256>>>(fproto);
    dim3 gg(CAP / 128, MROI);
    k_gemm<<<gg, 256, GEMM_SMEM>>>(vfeat);
    dim3 gc(GXC / SLABW, MROI);
    k_conv<<<gc, 256>>>();
    k_emit<<<1, 64>>>(rois, proto, out);
}

// round 12
// speedup vs baseline: 2.4236x; 1.2426x over previous
#include <cuda_runtime.h>
#include <cuda_bf16.h>
#include <math.h>
#include <cstdint>

// ---------------- problem constants ----------------
#define MROI   64
#define GPTS   8192        // 64*32*4
#define GXC    64
#define GYC    32
#define GZC    4
#define CDIM   128
#define NKERN  147         // 7*7*3
#define NZ     10
#define NY     400
#define NX     352
#define NCELL  (NZ*NY*NX)
#define NVOX   200000
#define CAP    2048
#define USTR   196         // 49 (kx,ky) groups x 4 (kz padded)
#define SLABW  8           // k_conv slab width in X (gather version)
#define WINX   (SLABW + 6) // slotmap x-window

#define NB     160         // padded B rows
#define BSTRH  40          // B smem row stride (uint16), 80 B

// dynamic smem layout for k_gemm (per CTA): 88064 B
#define A_OFF(b)    ((b) * 18432)                  // 128*36*4
#define BHI_OFF(b)  (36864 + (b) * 12800)          // 160*80
#define BLO_OFF(b)  (62464 + (b) * 12800)
#define GEMM_SMEM   88064

// ---------------- device scratch ----------------
__device__ int                g_v2p[NCELL];
__device__ int                g_cnt[MROI];
__device__ int                g_qlist[MROI * CAP];
__device__ int                g_vox[MROI * CAP];
__device__ float2             g_trig[MROI];
__device__ unsigned long long g_best[MROI];
__device__ float              g_U[MROI * CAP * USTR];
__device__ unsigned short     g_Whi[NB * CDIM];
__device__ unsigned short     g_Wlo[NB * CDIM];

// ---------------- helpers ----------------
__device__ __forceinline__ void grid_point_world_f(const float* __restrict__ r,
                                                   float cc, float ss, int p,
                                                   float& wx, float& wy, float& wz) {
    float dx = r[3] * 2.0f, dy = r[4] * 2.0f, dz = r[5];
    int i = p >> 7;
    int j = (p >> 2) & 31;
    int k = p & 3;
    float lx = ((i + 0.5f) / 64.0f) * dx - dx * 0.5f;
    float ly = ((j + 0.5f) / 32.0f) * dy - dy * 0.5f;
    float lz = ((k + 0.5f) / 4.0f)  * dz - dz * 0.5f;
    wx = lx * cc - ly * ss + r[0];
    wy = lx * ss + ly * cc + r[1];
    wz = lz + r[2];
}

__device__ __forceinline__ unsigned int ord_float(float f) {
    unsigned int u = __float_as_uint(f);
    return (u & 0x80000000u) ? ~u : (u | 0x80000000u);
}

__device__ __forceinline__ uint32_t smem_u32(const void* p) {
    uint32_t a;
    asm("{ .reg .u64 t; cvta.to.shared.u64 t, %1; cvt.u32.u64 %0, t; }" : "=r"(a) : "l"(p));
    return a;
}
__device__ __forceinline__ void cp_async16(uint32_t s, const void* g) {
    asm volatile("cp.async.cg.shared.global [%0], [%1], 16;" :: "r"(s), "l"(g));
}
#define CP_COMMIT()  asm volatile("cp.async.commit_group;" ::: "memory")
#define CP_WAIT(n)   asm volatile("cp.async.wait_group %0;" :: "n"(n) : "memory")

__device__ __forceinline__ uint32_t pack_bf16x2(float f0, float f1) {
    uint32_t r;
    asm("cvt.rn.bf16x2.f32 %0, %2, %1;" : "=r"(r) : "f"(f0), "f"(f1));
    return r;
}
__device__ __forceinline__ void split_pair(float f0, float f1, uint32_t& hi, uint32_t& lo) {
    hi = pack_bf16x2(f0, f1);
    float h0 = __uint_as_float(hi << 16);
    float h1 = __uint_as_float(hi & 0xFFFF0000u);
    lo = pack_bf16x2(f0 - h0, f1 - h1);
}

__device__ __forceinline__ void mma_bf16(float* c, const uint32_t* a, uint32_t b0, uint32_t b1) {
    asm volatile("mma.sync.aligned.m16n8k16.row.col.f32.bf16.bf16.f32 "
                 "{%0,%1,%2,%3}, {%4,%5,%6,%7}, {%8,%9}, {%0,%1,%2,%3};"
                 : "+f"(c[0]), "+f"(c[1]), "+f"(c[2]), "+f"(c[3])
                 : "r"(a[0]), "r"(a[1]), "r"(a[2]), "r"(a[3]), "r"(b0), "r"(b1));
}

// ---------------- kernel 1: init ----------------
__global__ __launch_bounds__(256) void k_init(const float* __restrict__ rois) {
    int i = blockIdx.x * blockDim.x + threadIdx.x;
    if (blockIdx.x == 0 && threadIdx.x < MROI) {
        g_cnt[threadIdx.x] = 0;
        g_best[threadIdx.x] = 0ull;
        double ang = (double)rois[threadIdx.x * 7 + 6];
        g_trig[threadIdx.x] = make_float2((float)cos(ang), (float)sin(ang));
    }
    for (int j = i; j < NCELL; j += gridDim.x * blockDim.x) g_v2p[j] = -1;
}

// ---------------- kernel 2: voxel scatter ----------------
__global__ __launch_bounds__(256) void k_scatter(const int* __restrict__ vc) {
    int i = blockIdx.x * blockDim.x + threadIdx.x;
    if (i >= NVOX) return;
    int zc = vc[i * 4 + 1];
    int yc = vc[i * 4 + 2];
    int xc = vc[i * 4 + 3];
    atomicMax(&g_v2p[(zc * NY + yc) * NX + xc], i);
}

// ---------------- kernel 3: compact valid points (warp-aggregated) ----------------
__global__ __launch_bounds__(256) void k_points(const float* __restrict__ rois) {
    int gid = blockIdx.x * blockDim.x + threadIdx.x;
    int m = gid >> 13;
    int p = gid & (GPTS - 1);
    int lane = threadIdx.x & 31;

    float2 tg = g_trig[m];
    float wx, wy, wz;
    grid_point_world_f(rois + m * 7, tg.x, tg.y, p, wx, wy, wz);
    float fx = floorf(__fdiv_rn(wx - 0.0f,  0.05f));
    float fy = floorf(__fdiv_rn(wy + 40.0f, 0.05f));
    float fz = floorf(__fdiv_rn(wz + 3.0f,  0.1f));
    int xc = (int)floorf(fx * 0.25f);
    int yc = (int)floorf(fy * 0.25f);
    int zc = (int)floorf(fz * 0.25f);

    bool valid = false;
    int pidx = -1;
    if (zc >= 0 && zc < NZ && yc >= 0 && yc < NY && xc >= 0 && xc < NX) {
        pidx = g_v2p[(zc * NY + yc) * NX + xc];
        valid = (pidx >= 0);
    }
    unsigned mask = __ballot_sync(0xFFFFFFFFu, valid);
    if (valid) {
        int leader = __ffs(mask) - 1;
        int base = 0;
        if (lane == leader) base = atomicAdd(&g_cnt[m], __popc(mask));
        base = __shfl_sync(mask, base, leader);
        int slot = base + __popc(mask & ((1u << lane) - 1u));
        if (slot < CAP) {
            g_qlist[m * CAP + slot] = p;
            g_vox[m * CAP + slot]   = pidx;
        }
    }
}

// ---------------- kernel 3.5: split W into bf16 hi/lo ----------------
__global__ __launch_bounds__(256) void k_prepb(const float* __restrict__ w) {
    int idx = blockIdx.x * blockDim.x + threadIdx.x;
    if (idx >= NB * CDIM) return;
    int row = idx >> 7;
    int col = idx & 127;
    float v = (row < NKERN) ? w[row * CDIM + col] : 0.0f;
    __nv_bfloat16 h = __float2bfloat16(v);
    float r = v - __bfloat162float(h);
    __nv_bfloat16 l = __float2bfloat16(r);
    g_Whi[idx] = __bfloat16_as_ushort(h);
    g_Wlo[idx] = __bfloat16_as_ushort(l);
}

// ---------------- kernel 4: split-bf16 tensor-core gathered GEMM ----------------
__global__ __launch_bounds__(256, 2) void k_gemm(const float* __restrict__ vfeat) {
    int m = blockIdx.y;
    int cnt = min(g_cnt[m], CAP);
    int q0 = blockIdx.x * 128;
    if (q0 >= cnt) return;

    extern __shared__ __align__(16) char dsm[];
    __shared__ int rowv[128];

    int t    = threadIdx.x;
    int wid  = t >> 5;
    int lane = t & 31;
    int g    = lane >> 2;
    int tt   = lane & 3;
    int mw   = wid & 3;
    int nw   = wid >> 2;
    int q0w  = mw * 32;
    int n0w  = nw * 80;

    if (t < 128) rowv[t] = (q0 + t < cnt) ? g_vox[m * CAP + q0 + t] : -1;
    __syncthreads();

    uint32_t dsm_u = smem_u32(dsm);

    #pragma unroll
    for (int i = 0; i < 4; i++) {
        int gi = t + 256 * i;
        int row = gi >> 3, q16 = gi & 7;
        if (rowv[row] < 0) {
            uint4 z = make_uint4(0u, 0u, 0u, 0u);
            *(uint4*)(dsm + A_OFF(0) + row * 144 + q16 * 16) = z;
            *(uint4*)(dsm + A_OFF(1) + row * 144 + q16 * 16) = z;
        }
    }

    #define ISSUE(ch, buf) do {                                                     \
        _Pragma("unroll")                                                           \
        for (int i = 0; i < 4; i++) {                                               \
            int gi = t + 256 * i;                                                   \
            int row = gi >> 3, q16 = gi & 7;                                        \
            int vr = rowv[row];                                                     \
            if (vr >= 0)                                                            \
                cp_async16(dsm_u + A_OFF(buf) + row * 144 + q16 * 16,               \
                           vfeat + (size_t)vr * CDIM + (ch) * 32 + q16 * 4);        \
        }                                                                           \
        _Pragma("unroll")                                                           \
        for (int i = 0; i < 5; i++) {                                               \
            int idx = t + 256 * i;                                                  \
            int mat = idx >= 640;                                                   \
            int gi = idx - (mat ? 640 : 0);                                         \
            int row = gi >> 2, q16 = gi & 3;                                        \
            const unsigned short* src = (mat ? g_Wlo : g_Whi)                       \
                                        + row * CDIM + (ch) * 32 + q16 * 8;         \
            uint32_t dst = dsm_u + (mat ? BLO_OFF(buf) : BHI_OFF(buf))              \
                           + row * 80 + q16 * 16;                                   \
            cp_async16(dst, src);                                                   \
        }                                                                           \
    } while (0)

    float acc[2][10][4];
    #pragma unroll
    for (int i = 0; i < 2; i++)
        #pragma unroll
        for (int j = 0; j < 10; j++)
            #pragma unroll
            for (int e = 0; e < 4; e++) acc[i][j][e] = 0.0f;

    ISSUE(0, 0); CP_COMMIT();

    #pragma unroll
    for (int ch = 0; ch < 4; ch++) {
        if (ch < 3) { ISSUE(ch + 1, (ch + 1) & 1); CP_COMMIT(); CP_WAIT(1); }
        else        { CP_WAIT(0); }
        __syncthreads();

        int buf = ch & 1;
        const char* abase = dsm + A_OFF(buf);
        const unsigned short* bh = (const unsigned short*)(dsm + BHI_OFF(buf));
        const unsigned short* bl = (const unsigned short*)(dsm + BLO_OFF(buf));

        #pragma unroll
        for (int ks = 0; ks < 2; ks++) {
            int k0 = ks * 16 + 2 * tt;
            uint32_t ahi[2][4], alo[2][4];
            #pragma unroll
            for (int mt = 0; mt < 2; mt++) {
                int r0 = q0w + mt * 16 + g;
                #pragma unroll
                for (int half = 0; half < 2; half++) {
                    float2 p0 = *(const float2*)(abase + r0 * 144 + (k0 + half * 8) * 4);
                    float2 p1 = *(const float2*)(abase + (r0 + 8) * 144 + (k0 + half * 8) * 4);
                    split_pair(p0.x, p0.y, ahi[mt][half * 2],     alo[mt][half * 2]);
                    split_pair(p1.x, p1.y, ahi[mt][half * 2 + 1], alo[mt][half * 2 + 1]);
                }
            }
            #pragma unroll
            for (int nt = 0; nt < 10; nt++) {
                int n = n0w + nt * 8 + g;
                uint32_t bh0 = *(const uint32_t*)(bh + n * BSTRH + k0);
                uint32_t bh1 = *(const uint32_t*)(bh + n * BSTRH + k0 + 8);
                uint32_t bl0 = *(const uint32_t*)(bl + n * BSTRH + k0);
                uint32_t bl1 = *(const uint32_t*)(bl + n * BSTRH + k0 + 8);
                #pragma unroll
                for (int mt = 0; mt < 2; mt++) {
                    mma_bf16(acc[mt][nt], ahi[mt], bh0, bh1);
                    mma_bf16(acc[mt][nt], ahi[mt], bl0, bl1);
                    mma_bf16(acc[mt][nt], alo[mt], bh0, bh1);
                }
            }
        }
        __syncthreads();
    }
    #undef ISSUE

    #pragma unroll
    for (int mt = 0; mt < 2; mt++) {
        #pragma unroll
        for (int e2 = 0; e2 < 2; e2++) {
            int row = q0 + q0w + mt * 16 + g + e2 * 8;
            if (row >= cnt) continue;
            float* urow = &g_U[((size_t)m * CAP + row) * USTR];
            #pragma unroll
            for (int nt = 0; nt < 10; nt++) {
                int col = n0w + nt * 8 + 2 * tt;
                if (col < NKERN)     urow[(col / 3) * 4 + col % 3] = acc[mt][nt][e2 * 2];
                int col1 = col + 1;
                if (col1 < NKERN)    urow[(col1 / 3) * 4 + col1 % 3] = acc[mt][nt][e2 * 2 + 1];
            }
        }
    }
}

// ---------------- kernel 5: slab GATHER conv + fused argmax (no atomics) ----------------
__global__ __launch_bounds__(256) void k_conv() {
    __shared__ int                slotmap[WINX * 128];   // 14 x-window * 32y * 4z
    __shared__ unsigned long long rk[256];

    int m  = blockIdx.y;
    int x0 = blockIdx.x * SLABW;
    int t  = threadIdx.x;
    int cnt = min(g_cnt[m], CAP);

    for (int i = t; i < WINX * 128; i += 256) slotmap[i] = -1;
    __syncthreads();
    for (int s = t; s < cnt; s += 256) {
        int p = g_qlist[m * CAP + s];
        int rel = (p >> 7) - (x0 - 3);
        if (rel >= 0 && rel < WINX) slotmap[rel * 128 + (p & 127)] = s;
    }
    __syncthreads();

    const float* ubase = &g_U[(size_t)m * CAP * USTR];

    // one (X,Y) column per thread (SLABW*32 == 256)
    int X = x0 + (t >> 5);
    int Y = t & 31;
    float a0 = 0.f, a1 = 0.f, a2v = 0.f, a3 = 0.f;
    #pragma unroll 1
    for (int dx = -3; dx <= 3; dx++) {
        int xp = X + dx;
        if (xp < 0 || xp >= GXC) continue;
        const int* smrow = &slotmap[(xp - x0 + 3) * 128];
        int kxg = (dx + 3) * 7;
        #pragma unroll
        for (int dy = -3; dy <= 3; dy++) {
            int yp = Y + dy;
            if (yp < 0 || yp >= GYC) continue;
            int4 sl = *(const int4*)&smrow[yp << 2];
            int goff = (kxg + dy + 3) * 4;
            if (sl.x >= 0) {   // z'=0 contributes to z=0 (u[1]), z=1 (u[0])
                const float* u = ubase + (size_t)sl.x * USTR + goff;
                a0 += u[1]; a1 += u[0];
            }
            if (sl.y >= 0) {   // z'=1
                const float* u = ubase + (size_t)sl.y * USTR + goff;
                a0 += u[2]; a1 += u[1]; a2v += u[0];
            }
            if (sl.z >= 0) {   // z'=2
                const float* u = ubase + (size_t)sl.z * USTR + goff;
                a1 += u[2]; a2v += u[1]; a3 += u[0];
            }
            if (sl.w >= 0) {   // z'=3
                const float* u = ubase + (size_t)sl.w * USTR + goff;
                a2v += u[2]; a3 += u[1];
            }
        }
    }

    unsigned long long best = 0ull;
    {
        int pb = (X << 7) + (Y << 2);
        unsigned long long k0 = ((unsigned long long)ord_float(a0)  << 32) | (unsigned int)(~pb);
        unsigned long long k1 = ((unsigned long long)ord_float(a1)  << 32) | (unsigned int)(~(pb + 1));
        unsigned long long k2 = ((unsigned long long)ord_float(a2v) << 32) | (unsigned int)(~(pb + 2));
        unsigned long long k3 = ((unsigned long long)ord_float(a3)  << 32) | (unsigned int)(~(pb + 3));
        best = k0;
        if (k1 > best) best = k1;
        if (k2 > best) best = k2;
        if (k3 > best) best = k3;
    }
    rk[t] = best;
    __syncthreads();
    if (t < 128) { if (rk[t + 128] > rk[t]) rk[t] = rk[t + 128]; }
    __syncthreads();
    if (t < 64)  { if (rk[t + 64]  > rk[t]) rk[t] = rk[t + 64]; }
    __syncthreads();
    if (t < 32) {
        unsigned long long b = rk[t];
        if (rk[t + 32] > b) b = rk[t + 32];
        #pragma unroll
        for (int o = 16; o > 0; o >>= 1) {
            unsigned long long other = __shfl_down_sync(0xFFFFFFFFu, b, o);
            if (other > b) b = other;
        }
        if (t == 0) atomicMax(&g_best[m], b);
    }
}

// ---------------- kernel 6: emit ----------------
__global__ __launch_bounds__(64) void k_emit(const float* __restrict__ rois,
                                             const float* __restrict__ proto,
                                             float* __restrict__ out) {
    int m = threadIdx.x;
    if (m >= MROI) return;
    unsigned long long key = g_best[m];
    int p = (int)(~(unsigned int)(key & 0xFFFFFFFFull));
    float2 tg = g_trig[m];
    float wx, wy, wz;
    grid_point_world_f(rois + m * 7, tg.x, tg.y, p, wx, wy, wz);
    out[m * 7 + 0] = wx;
    out[m * 7 + 1] = wy;
    out[m * 7 + 2] = wz;
    out[m * 7 + 3] = proto[3];
    out[m * 7 + 4] = proto[4];
    out[m * 7 + 5] = proto[5];
    out[m * 7 + 6] = proto[6];
}

// ---------------- launcher ----------------
extern "C" void kernel_launch(void* const* d_in, const int* in_sizes, int n_in,
                              void* d_out, int out_size) {
    const float* rois    = (const float*)d_in[0];
    const float* proto   = (const float*)d_in[1];
    const float* vfeat   = (const float*)d_in[2];
    const float* fproto  = (const float*)d_in[3];
    const int*   vcoords = (const int*)d_in[4];
    float* out = (float*)d_out;

    static bool attr_set = false;
    if (!attr_set) {
        cudaFuncSetAttribute(k_gemm, cudaFuncAttributeMaxDynamicSharedMemorySize, GEMM_SMEM);
        attr_set = true;
    }

    k_init<<<2048, 256>>>(rois);
    k_scatter<<<(NVOX + 255) / 256, 256>>>(vcoords);
    k_points<<<MROI * GPTS / 256, 256>>>(rois);
    k_prepb<<<(NB * CDIM + 255) / 256, 256>>>(fproto);
    dim3 gg(CAP / 128, MROI);
    k_gemm<<<gg, 256, GEMM_SMEM>>>(vfeat);
    dim3 gc(GXC / SLABW, MROI);
    k_conv<<<gc, 256>>>();
    k_emit<<<1, 64>>>(rois, proto, out);
}

// round 13
// speedup vs baseline: 3.8935x; 1.6065x over previous
#include <cuda_runtime.h>
#include <cuda_bf16.h>
#include <math.h>
#include <cstdint>

// ---------------- problem constants ----------------
#define MROI   64
#define GPTS   8192        // 64*32*4
#define GXC    64
#define GYC    32
#define GZC    4
#define CDIM   128
#define NKERN  147         // 7*7*3
#define NZ     10
#define NY     400
#define NX     352
#define NCELL  (NZ*NY*NX)
#define NVOX   200000
#define CAP    2048
#define USTR   196         // 49 (kx,ky) groups x 4 (kz padded)
#define SLABW  8           // k_conv slab width in X (gather version)
#define WINX   (SLABW + 6) // slotmap x-window

#define NB     160         // padded B rows
#define BSTRH  40          // B smem row stride (uint16), 80 B

// dynamic smem layout for k_gemm (per CTA): 88064 B
#define A_OFF(b)    ((b) * 18432)                  // 128*36*4
#define BHI_OFF(b)  (36864 + (b) * 12800)          // 160*80
#define BLO_OFF(b)  (62464 + (b) * 12800)
#define GEMM_SMEM   88064

// ---------------- device scratch ----------------
__device__ int                g_v2p[NCELL];
__device__ int                g_cnt[MROI];
__device__ int                g_qlist[MROI * CAP];
__device__ int                g_vox[MROI * CAP];
__device__ float2             g_trig[MROI];
__device__ unsigned long long g_best[MROI];
__device__ float              g_U[MROI * CAP * USTR];
__device__ unsigned short     g_Whi[NB * CDIM];
__device__ unsigned short     g_Wlo[NB * CDIM];

// ---------------- helpers ----------------
__device__ __forceinline__ void grid_point_world_f(const float* __restrict__ r,
                                                   float cc, float ss, int p,
                                                   float& wx, float& wy, float& wz) {
    float dx = r[3] * 2.0f, dy = r[4] * 2.0f, dz = r[5];
    int i = p >> 7;
    int j = (p >> 2) & 31;
    int k = p & 3;
    float lx = ((i + 0.5f) / 64.0f) * dx - dx * 0.5f;
    float ly = ((j + 0.5f) / 32.0f) * dy - dy * 0.5f;
    float lz = ((k + 0.5f) / 4.0f)  * dz - dz * 0.5f;
    wx = lx * cc - ly * ss + r[0];
    wy = lx * ss + ly * cc + r[1];
    wz = lz + r[2];
}

__device__ __forceinline__ unsigned int ord_float(float f) {
    unsigned int u = __float_as_uint(f);
    return (u & 0x80000000u) ? ~u : (u | 0x80000000u);
}

__device__ __forceinline__ uint32_t smem_u32(const void* p) {
    uint32_t a;
    asm("{ .reg .u64 t; cvta.to.shared.u64 t, %1; cvt.u32.u64 %0, t; }" : "=r"(a) : "l"(p));
    return a;
}
__device__ __forceinline__ void cp_async16(uint32_t s, const void* g) {
    asm volatile("cp.async.cg.shared.global [%0], [%1], 16;" :: "r"(s), "l"(g));
}
#define CP_COMMIT()  asm volatile("cp.async.commit_group;" ::: "memory")
#define CP_WAIT(n)   asm volatile("cp.async.wait_group %0;" :: "n"(n) : "memory")

__device__ __forceinline__ uint32_t pack_bf16x2(float f0, float f1) {
    uint32_t r;
    asm("cvt.rn.bf16x2.f32 %0, %2, %1;" : "=r"(r) : "f"(f0), "f"(f1));
    return r;
}
__device__ __forceinline__ void split_pair(float f0, float f1, uint32_t& hi, uint32_t& lo) {
    hi = pack_bf16x2(f0, f1);
    float h0 = __uint_as_float(hi << 16);
    float h1 = __uint_as_float(hi & 0xFFFF0000u);
    lo = pack_bf16x2(f0 - h0, f1 - h1);
}

__device__ __forceinline__ void mma_bf16(float* c, const uint32_t* a, uint32_t b0, uint32_t b1) {
    asm volatile("mma.sync.aligned.m16n8k16.row.col.f32.bf16.bf16.f32 "
                 "{%0,%1,%2,%3}, {%4,%5,%6,%7}, {%8,%9}, {%0,%1,%2,%3};"
                 : "+f"(c[0]), "+f"(c[1]), "+f"(c[2]), "+f"(c[3])
                 : "r"(a[0]), "r"(a[1]), "r"(a[2]), "r"(a[3]), "r"(b0), "r"(b1));
}

// ---------------- kernel 1: init + W split (fused) ----------------
__global__ __launch_bounds__(256) void k_init(const float* __restrict__ rois,
                                              const float* __restrict__ w) {
    int i = blockIdx.x * blockDim.x + threadIdx.x;
    if (blockIdx.x == 0 && threadIdx.x < MROI) {
        g_cnt[threadIdx.x] = 0;
        g_best[threadIdx.x] = 0ull;
        double ang = (double)rois[threadIdx.x * 7 + 6];
        g_trig[threadIdx.x] = make_float2((float)cos(ang), (float)sin(ang));
    }
    if (i < NB * CDIM) {   // fused k_prepb (first 80 blocks)
        int row = i >> 7;
        int col = i & 127;
        float v = (row < NKERN) ? w[row * CDIM + col] : 0.0f;
        __nv_bfloat16 h = __float2bfloat16(v);
        float r = v - __bfloat162float(h);
        __nv_bfloat16 l = __float2bfloat16(r);
        g_Whi[i] = __bfloat16_as_ushort(h);
        g_Wlo[i] = __bfloat16_as_ushort(l);
    }
    for (int j = i; j < NCELL; j += gridDim.x * blockDim.x) g_v2p[j] = -1;
}

// ---------------- kernel 2: voxel scatter ----------------
__global__ __launch_bounds__(256) void k_scatter(const int* __restrict__ vc) {
    int i = blockIdx.x * blockDim.x + threadIdx.x;
    if (i >= NVOX) return;
    int zc = vc[i * 4 + 1];
    int yc = vc[i * 4 + 2];
    int xc = vc[i * 4 + 3];
    atomicMax(&g_v2p[(zc * NY + yc) * NX + xc], i);
}

// ---------------- kernel 3: compact valid points (warp-aggregated) ----------------
__global__ __launch_bounds__(256) void k_points(const float* __restrict__ rois) {
    int gid = blockIdx.x * blockDim.x + threadIdx.x;
    int m = gid >> 13;
    int p = gid & (GPTS - 1);
    int lane = threadIdx.x & 31;

    float2 tg = g_trig[m];
    float wx, wy, wz;
    grid_point_world_f(rois + m * 7, tg.x, tg.y, p, wx, wy, wz);
    float fx = floorf(__fdiv_rn(wx - 0.0f,  0.05f));
    float fy = floorf(__fdiv_rn(wy + 40.0f, 0.05f));
    float fz = floorf(__fdiv_rn(wz + 3.0f,  0.1f));
    int xc = (int)floorf(fx * 0.25f);
    int yc = (int)floorf(fy * 0.25f);
    int zc = (int)floorf(fz * 0.25f);

    bool valid = false;
    int pidx = -1;
    if (zc >= 0 && zc < NZ && yc >= 0 && yc < NY && xc >= 0 && xc < NX) {
        pidx = g_v2p[(zc * NY + yc) * NX + xc];
        valid = (pidx >= 0);
    }
    unsigned mask = __ballot_sync(0xFFFFFFFFu, valid);
    if (valid) {
        int leader = __ffs(mask) - 1;
        int base = 0;
        if (lane == leader) base = atomicAdd(&g_cnt[m], __popc(mask));
        base = __shfl_sync(mask, base, leader);
        int slot = base + __popc(mask & ((1u << lane) - 1u));
        if (slot < CAP) {
            g_qlist[m * CAP + slot] = p;
            g_vox[m * CAP + slot]   = pidx;
        }
    }
}

// ---------------- kernel 4: split-bf16 tensor-core gathered GEMM ----------------
__global__ __launch_bounds__(256, 2) void k_gemm(const float* __restrict__ vfeat) {
    int m = blockIdx.y;
    int cnt = min(g_cnt[m], CAP);
    int q0 = blockIdx.x * 128;
    if (q0 >= cnt) return;

    extern __shared__ __align__(16) char dsm[];
    __shared__ int rowv[128];

    int t    = threadIdx.x;
    int wid  = t >> 5;
    int lane = t & 31;
    int g    = lane >> 2;
    int tt   = lane & 3;
    int mw   = wid & 3;
    int nw   = wid >> 2;
    int q0w  = mw * 32;
    int n0w  = nw * 80;

    if (t < 128) rowv[t] = (q0 + t < cnt) ? g_vox[m * CAP + q0 + t] : -1;
    __syncthreads();

    uint32_t dsm_u = smem_u32(dsm);

    #pragma unroll
    for (int i = 0; i < 4; i++) {
        int gi = t + 256 * i;
        int row = gi >> 3, q16 = gi & 7;
        if (rowv[row] < 0) {
            uint4 z = make_uint4(0u, 0u, 0u, 0u);
            *(uint4*)(dsm + A_OFF(0) + row * 144 + q16 * 16) = z;
            *(uint4*)(dsm + A_OFF(1) + row * 144 + q16 * 16) = z;
        }
    }

    #define ISSUE(ch, buf) do {                                                     \
        _Pragma("unroll")                                                           \
        for (int i = 0; i < 4; i++) {                                               \
            int gi = t + 256 * i;                                                   \
            int row = gi >> 3, q16 = gi & 7;                                        \
            int vr = rowv[row];                                                     \
            if (vr >= 0)                                                            \
                cp_async16(dsm_u + A_OFF(buf) + row * 144 + q16 * 16,               \
                           vfeat + (size_t)vr * CDIM + (ch) * 32 + q16 * 4);        \
        }                                                                           \
        _Pragma("unroll")                                                           \
        for (int i = 0; i < 5; i++) {                                               \
            int idx = t + 256 * i;                                                  \
            int mat = idx >= 640;                                                   \
            int gi = idx - (mat ? 640 : 0);                                         \
            int row = gi >> 2, q16 = gi & 3;                                        \
            const unsigned short* src = (mat ? g_Wlo : g_Whi)                       \
                                        + row * CDIM + (ch) * 32 + q16 * 8;         \
            uint32_t dst = dsm_u + (mat ? BLO_OFF(buf) : BHI_OFF(buf))              \
                           + row * 80 + q16 * 16;                                   \
            cp_async16(dst, src);                                                   \
        }                                                                           \
    } while (0)

    float acc[2][10][4];
    #pragma unroll
    for (int i = 0; i < 2; i++)
        #pragma unroll
        for (int j = 0; j < 10; j++)
            #pragma unroll
            for (int e = 0; e < 4; e++) acc[i][j][e] = 0.0f;

    ISSUE(0, 0); CP_COMMIT();

    #pragma unroll
    for (int ch = 0; ch < 4; ch++) {
        if (ch < 3) { ISSUE(ch + 1, (ch + 1) & 1); CP_COMMIT(); CP_WAIT(1); }
        else        { CP_WAIT(0); }
        __syncthreads();

        int buf = ch & 1;
        const char* abase = dsm + A_OFF(buf);
        const unsigned short* bh = (const unsigned short*)(dsm + BHI_OFF(buf));
        const unsigned short* bl = (const unsigned short*)(dsm + BLO_OFF(buf));

        #pragma unroll
        for (int ks = 0; ks < 2; ks++) {
            int k0 = ks * 16 + 2 * tt;
            uint32_t ahi[2][4], alo[2][4];
            #pragma unroll
            for (int mt = 0; mt < 2; mt++) {
                int r0 = q0w + mt * 16 + g;
                #pragma unroll
                for (int half = 0; half < 2; half++) {
                    float2 p0 = *(const float2*)(abase + r0 * 144 + (k0 + half * 8) * 4);
                    float2 p1 = *(const float2*)(abase + (r0 + 8) * 144 + (k0 + half * 8) * 4);
                    split_pair(p0.x, p0.y, ahi[mt][half * 2],     alo[mt][half * 2]);
                    split_pair(p1.x, p1.y, ahi[mt][half * 2 + 1], alo[mt][half * 2 + 1]);
                }
            }
            #pragma unroll
            for (int nt = 0; nt < 10; nt++) {
                int n = n0w + nt * 8 + g;
                uint32_t bh0 = *(const uint32_t*)(bh + n * BSTRH + k0);
                uint32_t bh1 = *(const uint32_t*)(bh + n * BSTRH + k0 + 8);
                uint32_t bl0 = *(const uint32_t*)(bl + n * BSTRH + k0);
                uint32_t bl1 = *(const uint32_t*)(bl + n * BSTRH + k0 + 8);
                #pragma unroll
                for (int mt = 0; mt < 2; mt++) {
                    mma_bf16(acc[mt][nt], ahi[mt], bh0, bh1);
                    mma_bf16(acc[mt][nt], ahi[mt], bl0, bl1);
                    mma_bf16(acc[mt][nt], alo[mt], bh0, bh1);
                }
            }
        }
        __syncthreads();
    }
    #undef ISSUE

    // ---- epilogue: stage in smem (64 rows/phase), copy out coalesced ----
    // After the loop's trailing __syncthreads all warps are done with dsm.
    float* stage = (float*)dsm;     // 64 * 196 floats = 50176 B
    #pragma unroll 1
    for (int phase = 0; phase < 2; phase++) {
        if ((mw >> 1) == phase) {
            int rbase = (mw & 1) * 32;
            #pragma unroll
            for (int mt = 0; mt < 2; mt++) {
                #pragma unroll
                for (int e2 = 0; e2 < 2; e2++) {
                    int srow = rbase + mt * 16 + g + e2 * 8;
                    float* srp = stage + srow * USTR;
                    #pragma unroll
                    for (int nt = 0; nt < 10; nt++) {
                        int col = n0w + nt * 8 + 2 * tt;
                        if (col < NKERN)
                            srp[(col / 3) * 4 + col % 3] = acc[mt][nt][e2 * 2];
                        int col1 = col + 1;
                        if (col1 < NKERN)
                            srp[(col1 / 3) * 4 + col1 % 3] = acc[mt][nt][e2 * 2 + 1];
                    }
                }
            }
        }
        __syncthreads();
        // coalesced copy-out: 64 rows * 49 float4
        float4* dst = (float4*)&g_U[((size_t)m * CAP + q0 + phase * 64) * USTR];
        const float4* src = (const float4*)stage;
        for (int i = t; i < 64 * 49; i += 256) dst[i] = src[i];
        __syncthreads();
    }
}

// ---------------- kernel 5: slab GATHER conv + fused argmax (no atomics) ----------------
__global__ __launch_bounds__(256) void k_conv() {
    __shared__ int                slotmap[WINX * 128];   // 14 x-window * 32y * 4z
    __shared__ unsigned long long rk[256];

    int m  = blockIdx.y;
    int x0 = blockIdx.x * SLABW;
    int t  = threadIdx.x;
    int cnt = min(g_cnt[m], CAP);

    for (int i = t; i < WINX * 128; i += 256) slotmap[i] = -1;
    __syncthreads();
    for (int s = t; s < cnt; s += 256) {
        int p = g_qlist[m * CAP + s];
        int rel = (p >> 7) - (x0 - 3);
        if (rel >= 0 && rel < WINX) slotmap[rel * 128 + (p & 127)] = s;
    }
    __syncthreads();

    const float* ubase = &g_U[(size_t)m * CAP * USTR];

    int X = x0 + (t >> 5);
    int Y = t & 31;
    float a0 = 0.f, a1 = 0.f, a2v = 0.f, a3 = 0.f;
    #pragma unroll 1
    for (int dx = -3; dx <= 3; dx++) {
        int xp = X + dx;
        if (xp < 0 || xp >= GXC) continue;
        const int* smrow = &slotmap[(xp - x0 + 3) * 128];
        int kxg = (dx + 3) * 7;
        #pragma unroll
        for (int dy = -3; dy <= 3; dy++) {
            int yp = Y + dy;
            if (yp < 0 || yp >= GYC) continue;
            int4 sl = *(const int4*)&smrow[yp << 2];
            int goff = (kxg + dy + 3) * 4;
            if (sl.x >= 0) {
                const float* u = ubase + (size_t)sl.x * USTR + goff;
                a0 += u[1]; a1 += u[0];
            }
            if (sl.y >= 0) {
                const float* u = ubase + (size_t)sl.y * USTR + goff;
                a0 += u[2]; a1 += u[1]; a2v += u[0];
            }
            if (sl.z >= 0) {
                const float* u = ubase + (size_t)sl.z * USTR + goff;
                a1 += u[2]; a2v += u[1]; a3 += u[0];
            }
            if (sl.w >= 0) {
                const float* u = ubase + (size_t)sl.w * USTR + goff;
                a2v += u[2]; a3 += u[1];
            }
        }
    }

    unsigned long long best = 0ull;
    {
        int pb = (X << 7) + (Y << 2);
        unsigned long long k0 = ((unsigned long long)ord_float(a0)  << 32) | (unsigned int)(~pb);
        unsigned long long k1 = ((unsigned long long)ord_float(a1)  << 32) | (unsigned int)(~(pb + 1));
        unsigned long long k2 = ((unsigned long long)ord_float(a2v) << 32) | (unsigned int)(~(pb + 2));
        unsigned long long k3 = ((unsigned long long)ord_float(a3)  << 32) | (unsigned int)(~(pb + 3));
        best = k0;
        if (k1 > best) best = k1;
        if (k2 > best) best = k2;
        if (k3 > best) best = k3;
    }
    rk[t] = best;
    __syncthreads();
    if (t < 128) { if (rk[t + 128] > rk[t]) rk[t] = rk[t + 128]; }
    __syncthreads();
    if (t < 64)  { if (rk[t + 64]  > rk[t]) rk[t] = rk[t + 64]; }
    __syncthreads();
    if (t < 32) {
        unsigned long long b = rk[t];
        if (rk[t + 32] > b) b = rk[t + 32];
        #pragma unroll
        for (int o = 16; o > 0; o >>= 1) {
            unsigned long long other = __shfl_down_sync(0xFFFFFFFFu, b, o);
            if (other > b) b = other;
        }
        if (t == 0) atomicMax(&g_best[m], b);
    }
}

// ---------------- kernel 6: emit ----------------
__global__ __launch_bounds__(64) void k_emit(const float* __restrict__ rois,
                                             const float* __restrict__ proto,
                                             float* __restrict__ out) {
    int m = threadIdx.x;
    if (m >= MROI) return;
    unsigned long long key = g_best[m];
    int p = (int)(~(unsigned int)(key & 0xFFFFFFFFull));
    float2 tg = g_trig[m];
    float wx, wy, wz;
    grid_point_world_f(rois + m * 7, tg.x, tg.y, p, wx, wy, wz);
    out[m * 7 + 0] = wx;
    out[m * 7 + 1] = wy;
    out[m * 7 + 2] = wz;
    out[m * 7 + 3] = proto[3];
    out[m * 7 + 4] = proto[4];
    out[m * 7 + 5] = proto[5];
    out[m * 7 + 6] = proto[6];
}

// ---------------- launcher ----------------
extern "C" void kernel_launch(void* const* d_in, const int* in_sizes, int n_in,
                              void* d_out, int out_size) {
    const float* rois    = (const float*)d_in[0];
    const float* proto   = (const float*)d_in[1];
    const float* vfeat   = (const float*)d_in[2];
    const float* fproto  = (const float*)d_in[3];
    const int*   vcoords = (const int*)d_in[4];
    float* out = (float*)d_out;

    static bool attr_set = false;
    if (!attr_set) {
        cudaFuncSetAttribute(k_gemm, cudaFuncAttributeMaxDynamicSharedMemorySize, GEMM_SMEM);
        attr_set = true;
    }

    k_init<<<2048, 256>>>(rois, fproto);
    k_scatter<<<(NVOX + 255) / 256, 256>>>(vcoords);
    k_points<<<MROI * GPTS / 256, 256>>>(rois);
    dim3 gg(CAP / 128, MROI);
    k_gemm<<<gg, 256, GEMM_SMEM>>>(vfeat);
    dim3 gc(GXC / SLABW, MROI);
    k_conv<<<gc, 256>>>();
    k_emit<<<1, 64>>>(rois, proto, out);
}